// round 6
// baseline (speedup 1.0000x reference)
#include <cuda_runtime.h>
#include <math.h>
#include <stdint.h>

// ---------------------------------------------------------------------------
// DeBERTa layer, fp32 SIMT baseline.
// B=16 S=512 H=768 NH=12 DH=64 P=512 I=3072.
// scores[i,j] = q_i.k_j + q_i.PK[i-j+P] + k_j.PQ[j-i+P]   (no clipping: |i-j|<=511)
// ---------------------------------------------------------------------------

constexpr int kB  = 16;
constexpr int kS  = 512;
constexpr int kH  = 768;
constexpr int kNH = 12;
constexpr int kDH = 64;
constexpr int kP  = 512;
constexpr int kI  = 3072;
constexpr int kBS = kB * kS;    // 8192
constexpr int kBH = kB * kNH;   // 192
constexpr float kScale = 0.07216878364870322f;  // 1/sqrt(3*64)

// ---- scratch layout (one big __device__ array; no allocations anywhere) ----
constexpr size_t SZ_QKV = (size_t)kBH * kS * kDH;        // 6,291,456
constexpr size_t SZ_POS = (size_t)kNH * 2 * kP * kDH;    //   786,432
constexpr size_t SZ_S   = (size_t)kBH * kS * kS;         // 50,331,648
constexpr size_t SZ_CP  = (size_t)kBH * kS * 2 * kP;     // 100,663,296

constexpr size_t OFF_Q   = 0;
constexpr size_t OFF_K   = OFF_Q + SZ_QKV;
constexpr size_t OFF_V   = OFF_K + SZ_QKV;
constexpr size_t OFF_PK  = OFF_V + SZ_QKV;
constexpr size_t OFF_PQ  = OFF_PK + SZ_POS;
constexpr size_t OFF_S   = OFF_PQ + SZ_POS;   // c2c -> scores -> probs (in place)
constexpr size_t OFF_C2P = OFF_S + SZ_S;
constexpr size_t OFF_P2C = OFF_C2P + SZ_CP;
constexpr size_t OFF_CTX = OFF_P2C + SZ_CP;
constexpr size_t OFF_T1  = OFF_CTX + SZ_QKV;  // attn_out, later FFN2 out
constexpr size_t OFF_H1  = OFF_T1 + SZ_QKV;
constexpr size_t OFF_F1  = OFF_C2P;           // alias: c2p_all dead after assemble
constexpr size_t TOTAL   = OFF_H1 + SZ_QKV;   // 290,979,840 floats ~= 1.16 GB

__device__ float g_scratch[TOTAL];

enum { EPI_NONE = 0, EPI_GELU = 1, EPI_QKV = 2, EPI_POS = 3, EPI_CTX = 4 };

// ---------------------------------------------------------------------------
// Generic tiled SGEMM: C = epi(A @ B (+bias)), optional B-transposed (A@B^T),
// optional batching via blockIdx.z (element strides). All tile dims divide the
// problem dims exactly for every launch below (no bounds checks needed).
// ---------------------------------------------------------------------------
template<int BM, int BN, int BK, int TM, int TN, bool TB, int EPI>
__global__ __launch_bounds__((BM / TM) * (BN / TN))
void gemm_kernel(const float* __restrict__ Aex, size_t aOff,
                 const float* __restrict__ Bex, size_t bOff,
                 const float* __restrict__ bias,
                 float* __restrict__ Cex, size_t cOff,
                 int M, int N, int K,
                 size_t aStride, size_t bStride, int bMod, size_t cStride)
{
    constexpr int THREADS = (BM / TM) * (BN / TN);
    __shared__ __align__(16) float As[BK][BM + 4];
    __shared__ __align__(16) float Bs[BK][BN + 4];

    const float* A  = Aex ? Aex : (const float*)g_scratch + aOff;
    const float* Bp = Bex ? Bex : (const float*)g_scratch + bOff;
    float*       C  = Cex ? Cex : g_scratch + cOff;

    const int z = blockIdx.z;
    A  += (size_t)z * aStride;
    Bp += (size_t)(z % bMod) * bStride;

    const int m0  = blockIdx.y * BM;
    const int n0  = blockIdx.x * BN;
    const int tid = threadIdx.x;

    float acc[TM][TN];
#pragma unroll
    for (int i = 0; i < TM; i++)
#pragma unroll
        for (int j = 0; j < TN; j++) acc[i][j] = 0.f;

    for (int k0 = 0; k0 < K; k0 += BK) {
        // --- load A tile [BM x BK], store transposed As[k][m] ---
        constexpr int LA = (BM * BK) / (4 * THREADS);
#pragma unroll
        for (int r = 0; r < LA; r++) {
            int idx = tid + r * THREADS;
            int row = idx / (BK / 4);
            int kg  = idx % (BK / 4);
            const float4 v = *reinterpret_cast<const float4*>(
                &A[(size_t)(m0 + row) * K + k0 + kg * 4]);
            As[kg * 4 + 0][row] = v.x; As[kg * 4 + 1][row] = v.y;
            As[kg * 4 + 2][row] = v.z; As[kg * 4 + 3][row] = v.w;
        }
        if constexpr (!TB) {
            // B is [K,N] row-major: direct copy Bs[k][n]
            constexpr int LB = (BK * BN) / (4 * THREADS);
#pragma unroll
            for (int r = 0; r < LB; r++) {
                int idx = tid + r * THREADS;
                int kr  = idx / (BN / 4);
                int ng  = idx % (BN / 4);
                const float4 v = *reinterpret_cast<const float4*>(
                    &Bp[(size_t)(k0 + kr) * N + n0 + ng * 4]);
                Bs[kr][ng * 4 + 0] = v.x; Bs[kr][ng * 4 + 1] = v.y;
                Bs[kr][ng * 4 + 2] = v.z; Bs[kr][ng * 4 + 3] = v.w;
            }
        } else {
            // B is [N,K] row-major (A@B^T): transpose into Bs[k][n]
            constexpr int LB = (BN * BK) / (4 * THREADS);
#pragma unroll
            for (int r = 0; r < LB; r++) {
                int idx = tid + r * THREADS;
                int row = idx / (BK / 4);
                int kg  = idx % (BK / 4);
                const float4 v = *reinterpret_cast<const float4*>(
                    &Bp[(size_t)(n0 + row) * K + k0 + kg * 4]);
                Bs[kg * 4 + 0][row] = v.x; Bs[kg * 4 + 1][row] = v.y;
                Bs[kg * 4 + 2][row] = v.z; Bs[kg * 4 + 3][row] = v.w;
            }
        }
        __syncthreads();

        const int tx = tid % (BN / TN);
        const int ty = tid / (BN / TN);
#pragma unroll
        for (int k = 0; k < BK; k++) {
            float a[TM], b[TN];
#pragma unroll
            for (int i = 0; i < TM; i += 4) {
                const float4 v = *reinterpret_cast<const float4*>(&As[k][ty * TM + i]);
                a[i] = v.x; a[i + 1] = v.y; a[i + 2] = v.z; a[i + 3] = v.w;
            }
#pragma unroll
            for (int j = 0; j < TN; j += 4) {
                const float4 v = *reinterpret_cast<const float4*>(&Bs[k][tx * TN + j]);
                b[j] = v.x; b[j + 1] = v.y; b[j + 2] = v.z; b[j + 3] = v.w;
            }
#pragma unroll
            for (int i = 0; i < TM; i++)
#pragma unroll
                for (int j = 0; j < TN; j++)
                    acc[i][j] = fmaf(a[i], b[j], acc[i][j]);
        }
        __syncthreads();
    }

    // --- epilogue ---
    const int tx = tid % (BN / TN);
    const int ty = tid / (BN / TN);
#pragma unroll
    for (int i = 0; i < TM; i++) {
        const int m = m0 + ty * TM + i;
#pragma unroll
        for (int j = 0; j < TN; j++) {
            const int n = n0 + tx * TN + j;
            float v = acc[i][j];
            if (bias) v += bias[n];
            if constexpr (EPI == EPI_GELU)
                v = 0.5f * v * (1.f + erff(v * 0.70710678118654752f));
            size_t o;
            if constexpr (EPI == EPI_QKV) {          // [B*S,H] -> [B,NH,S,DH]
                const int bb = m >> 9, s = m & 511, h = n >> 6, d = n & 63;
                o = ((size_t)(bb * kNH + h) * kS + s) * kDH + d;
            } else if constexpr (EPI == EPI_POS) {   // [2P,H] -> [NH,2P,DH]
                const int h = n >> 6, d = n & 63;
                o = ((size_t)h * (2 * kP) + m) * kDH + d;
            } else if constexpr (EPI == EPI_CTX) {   // [S,DH] per bh -> [B,S,H]
                const int bb = z / kNH, h = z % kNH;
                o = ((size_t)bb * kS + m) * kH + h * kDH + n;
            } else {
                o = (size_t)z * cStride + (size_t)m * N + n;
            }
            C[o] = v;
        }
    }
}

// ---------------------------------------------------------------------------
// Assemble: scores = (c2c + gather(c2p_all) + gather(p2c_all)) * scale, mask.
// In place on the c2c buffer. 32x32 tiles; p2c's diagonal gather is staged
// through a transposed smem tile so every global read is (reverse-)contiguous.
// ---------------------------------------------------------------------------
__global__ void assemble_kernel(const float* __restrict__ mask)
{
    const int z  = blockIdx.z;
    const int i0 = blockIdx.y * 32;
    const int j0 = blockIdx.x * 32;
    const int tx = threadIdx.x;   // 0..31
    const int ty = threadIdx.y;   // 0..7

    __shared__ float p2cT[32][33];
    const float* P2Cz = g_scratch + OFF_P2C + (size_t)z * kS * (2 * kP);
#pragma unroll
    for (int jj = ty; jj < 32; jj += 8) {
        const int j = j0 + jj;
        // p2c[i,j] = p2c_all[j, j-i+P]; i = i0+tx -> reverse-contiguous read
        p2cT[jj][tx] = P2Cz[(size_t)j * (2 * kP) + (j - (i0 + tx) + kP)];
    }
    __syncthreads();

    const float* C2Pz = g_scratch + OFF_C2P + (size_t)z * kS * (2 * kP);
    float* Sz = g_scratch + OFF_S + (size_t)z * kS * kS;
    const float mj = mask[(size_t)(z / kNH) * kS + (j0 + tx)];
#pragma unroll
    for (int ii = ty; ii < 32; ii += 8) {
        const int i = i0 + ii;
        const int j = j0 + tx;
        float s = Sz[(size_t)i * kS + j]
                + C2Pz[(size_t)i * (2 * kP) + (i - j + kP)]
                + p2cT[tx][ii];
        s *= kScale;
        if (mj <= 0.f) s = -1e9f;
        Sz[(size_t)i * kS + j] = s;
    }
}

// ---------------------------------------------------------------------------
// Row softmax over the last axis (512), in place. One block per row.
// ---------------------------------------------------------------------------
__global__ void softmax_kernel()
{
    const size_t row = blockIdx.x;
    float* r = g_scratch + OFF_S + row * kS;
    const int t = threadIdx.x;
    float v0 = r[t], v1 = r[t + 256];

    __shared__ float red[256];
    red[t] = fmaxf(v0, v1);
    __syncthreads();
    for (int s = 128; s > 0; s >>= 1) {
        if (t < s) red[t] = fmaxf(red[t], red[t + s]);
        __syncthreads();
    }
    const float mx = red[0];
    __syncthreads();

    const float e0 = expf(v0 - mx), e1 = expf(v1 - mx);
    red[t] = e0 + e1;
    __syncthreads();
    for (int s = 128; s > 0; s >>= 1) {
        if (t < s) red[t] += red[t + s];
        __syncthreads();
    }
    const float inv = 1.f / red[0];
    r[t] = e0 * inv;
    r[t + 256] = e1 * inv;
}

// ---------------------------------------------------------------------------
// out = LayerNorm(X + Y) * g + b. One block (256 threads) per 768-wide row.
// ---------------------------------------------------------------------------
__global__ void add_ln_kernel(const float* __restrict__ Xex, size_t xOff, size_t yOff,
                              const float* __restrict__ g, const float* __restrict__ bb,
                              float* __restrict__ outEx, size_t outOff)
{
    const float* X = Xex ? Xex : (const float*)g_scratch + xOff;
    const float* Y = (const float*)g_scratch + yOff;
    float* O = outEx ? outEx : g_scratch + outOff;

    const size_t off = (size_t)blockIdx.x * kH;
    const int t = threadIdx.x;
    const float v0 = X[off + t]       + Y[off + t];
    const float v1 = X[off + t + 256] + Y[off + t + 256];
    const float v2 = X[off + t + 512] + Y[off + t + 512];

    __shared__ float red[256];
    red[t] = v0 + v1 + v2;
    __syncthreads();
    for (int s = 128; s > 0; s >>= 1) {
        if (t < s) red[t] += red[t + s];
        __syncthreads();
    }
    const float mean = red[0] * (1.f / 768.f);
    __syncthreads();

    const float d0 = v0 - mean, d1 = v1 - mean, d2 = v2 - mean;
    red[t] = d0 * d0 + d1 * d1 + d2 * d2;
    __syncthreads();
    for (int s = 128; s > 0; s >>= 1) {
        if (t < s) red[t] += red[t + s];
        __syncthreads();
    }
    const float rstd = rsqrtf(red[0] * (1.f / 768.f) + 1e-7f);

    O[off + t]       = d0 * rstd * g[t]       + bb[t];
    O[off + t + 256] = d1 * rstd * g[t + 256] + bb[t + 256];
    O[off + t + 512] = d2 * rstd * g[t + 512] + bb[t + 512];
}

// ---------------------------------------------------------------------------
extern "C" void kernel_launch(void* const* d_in, const int* in_sizes, int n_in,
                              void* d_out, int out_size)
{
    const float* hs  = (const float*)d_in[0];
    const float* am  = (const float*)d_in[1];
    const float* pe  = (const float*)d_in[2];
    const float* Wq  = (const float*)d_in[3];
    const float* bq  = (const float*)d_in[4];
    const float* Wk  = (const float*)d_in[5];
    const float* bk  = (const float*)d_in[6];
    const float* Wv  = (const float*)d_in[7];
    const float* bv  = (const float*)d_in[8];
    const float* Wpk = (const float*)d_in[9];
    const float* Wpq = (const float*)d_in[10];
    const float* Wo  = (const float*)d_in[11];
    const float* bo  = (const float*)d_in[12];
    const float* g1  = (const float*)d_in[13];
    const float* be1 = (const float*)d_in[14];
    const float* W1  = (const float*)d_in[15];
    const float* b1  = (const float*)d_in[16];
    const float* W2  = (const float*)d_in[17];
    const float* b2  = (const float*)d_in[18];
    const float* g2  = (const float*)d_in[19];
    const float* be2 = (const float*)d_in[20];
    float* out = (float*)d_out;

    // --- QKV projections: [8192,768]@[768,768] -> head layout ---
    gemm_kernel<128,128,16,8,8,false,EPI_QKV><<<dim3(kH/128, kBS/128, 1), 256>>>(
        hs, 0, Wq, 0, bq, nullptr, OFF_Q, kBS, kH, kH, 0, 0, 1, 0);
    gemm_kernel<128,128,16,8,8,false,EPI_QKV><<<dim3(kH/128, kBS/128, 1), 256>>>(
        hs, 0, Wk, 0, bk, nullptr, OFF_K, kBS, kH, kH, 0, 0, 1, 0);
    gemm_kernel<128,128,16,8,8,false,EPI_QKV><<<dim3(kH/128, kBS/128, 1), 256>>>(
        hs, 0, Wv, 0, bv, nullptr, OFF_V, kBS, kH, kH, 0, 0, 1, 0);

    // --- relative position projections: [1024,768]@[768,768] -> [NH,2P,DH] ---
    gemm_kernel<128,128,16,8,8,false,EPI_POS><<<dim3(kH/128, (2*kP)/128, 1), 256>>>(
        pe, 0, Wpk, 0, nullptr, nullptr, OFF_PK, 2*kP, kH, kH, 0, 0, 1, 0);
    gemm_kernel<128,128,16,8,8,false,EPI_POS><<<dim3(kH/128, (2*kP)/128, 1), 256>>>(
        pe, 0, Wpq, 0, nullptr, nullptr, OFF_PQ, 2*kP, kH, kH, 0, 0, 1, 0);

    // --- c2c: per (b,h)  Q[512,64] @ K[512,64]^T ---
    gemm_kernel<128,128,16,8,8,true,EPI_NONE><<<dim3(kS/128, kS/128, kBH), 256>>>(
        nullptr, OFF_Q, nullptr, OFF_K, nullptr, nullptr, OFF_S, kS, kS, kDH,
        (size_t)kS*kDH, (size_t)kS*kDH, kBH, (size_t)kS*kS);
    // --- c2p_all: Q @ PK_h^T -> [bh,512,1024] ---
    gemm_kernel<128,128,16,8,8,true,EPI_NONE><<<dim3((2*kP)/128, kS/128, kBH), 256>>>(
        nullptr, OFF_Q, nullptr, OFF_PK, nullptr, nullptr, OFF_C2P, kS, 2*kP, kDH,
        (size_t)kS*kDH, (size_t)(2*kP)*kDH, kNH, (size_t)kS*(2*kP));
    // --- p2c_all: K @ PQ_h^T -> [bh,512,1024] ---
    gemm_kernel<128,128,16,8,8,true,EPI_NONE><<<dim3((2*kP)/128, kS/128, kBH), 256>>>(
        nullptr, OFF_K, nullptr, OFF_PQ, nullptr, nullptr, OFF_P2C, kS, 2*kP, kDH,
        (size_t)kS*kDH, (size_t)(2*kP)*kDH, kNH, (size_t)kS*(2*kP));

    // --- assemble (+scale, +mask), then softmax, both in place on scores ---
    assemble_kernel<<<dim3(kS/32, kS/32, kBH), dim3(32, 8)>>>(am);
    softmax_kernel<<<kBH * kS, 256>>>();

    // --- ctx = probs @ V -> merged-head [B,S,H] ---
    gemm_kernel<128,64,16,8,4,false,EPI_CTX><<<dim3(1, kS/128, kBH), 256>>>(
        nullptr, OFF_S, nullptr, OFF_V, nullptr, nullptr, OFF_CTX, kS, kDH, kS,
        (size_t)kS*kS, (size_t)kS*kDH, kBH, 0);

    // --- output projection + residual LN1 ---
    gemm_kernel<128,128,16,8,8,false,EPI_NONE><<<dim3(kH/128, kBS/128, 1), 256>>>(
        nullptr, OFF_CTX, Wo, 0, bo, nullptr, OFF_T1, kBS, kH, kH, 0, 0, 1, 0);
    add_ln_kernel<<<kBS, 256>>>(hs, 0, OFF_T1, g1, be1, nullptr, OFF_H1);

    // --- FFN ---
    gemm_kernel<128,128,16,8,8,false,EPI_GELU><<<dim3(kI/128, kBS/128, 1), 256>>>(
        nullptr, OFF_H1, W1, 0, b1, nullptr, OFF_F1, kBS, kI, kH, 0, 0, 1, 0);
    gemm_kernel<128,128,16,8,8,false,EPI_NONE><<<dim3(kH/128, kBS/128, 1), 256>>>(
        nullptr, OFF_F1, W2, 0, b2, nullptr, OFF_T1, kBS, kH, kI, 0, 0, 1, 0);
    add_ln_kernel<<<kBS, 256>>>(nullptr, OFF_H1, OFF_T1, g2, be2, out, 0);
}

// round 7
// speedup vs baseline: 2.6473x; 2.6473x over previous
#include <cuda_runtime.h>
#include <math.h>
#include <stdint.h>

// ---------------------------------------------------------------------------
// DeBERTa layer, tf32 tensor-core (mma.sync m16n8k8) implementation.
// B=16 S=512 H=768 NH=12 DH=64 P=512 I=3072.
// scores[i,j] = q_i.k_j + q_i.PK[i-j+P] + k_j.PQ[j-i+P]   (no clipping: |i-j|<=511)
// ---------------------------------------------------------------------------

constexpr int kB  = 16;
constexpr int kS  = 512;
constexpr int kH  = 768;
constexpr int kNH = 12;
constexpr int kDH = 64;
constexpr int kP  = 512;
constexpr int kI  = 3072;
constexpr int kBS = kB * kS;    // 8192
constexpr int kBH = kB * kNH;   // 192
constexpr float kScale = 0.07216878364870322f;  // 1/sqrt(3*64)

// ---- scratch layout (one big __device__ array; no allocations anywhere) ----
constexpr size_t SZ_QKV = (size_t)kBH * kS * kDH;        // 6,291,456
constexpr size_t SZ_POS = (size_t)kNH * 2 * kP * kDH;    //   786,432
constexpr size_t SZ_S   = (size_t)kBH * kS * kS;         // 50,331,648
constexpr size_t SZ_CP  = (size_t)kBH * kS * 2 * kP;     // 100,663,296

constexpr size_t OFF_Q   = 0;
constexpr size_t OFF_K   = OFF_Q + SZ_QKV;
constexpr size_t OFF_V   = OFF_K + SZ_QKV;
constexpr size_t OFF_PK  = OFF_V + SZ_QKV;
constexpr size_t OFF_PQ  = OFF_PK + SZ_POS;
constexpr size_t OFF_S   = OFF_PQ + SZ_POS;   // c2c -> scores -> probs (in place)
constexpr size_t OFF_C2P = OFF_S + SZ_S;
constexpr size_t OFF_P2C = OFF_C2P + SZ_CP;
constexpr size_t OFF_CTX = OFF_P2C + SZ_CP;
constexpr size_t OFF_T1  = OFF_CTX + SZ_QKV;  // attn_out, later FFN2 out
constexpr size_t OFF_H1  = OFF_T1 + SZ_QKV;
constexpr size_t OFF_F1  = OFF_C2P;           // alias: c2p_all dead after assemble
constexpr size_t TOTAL   = OFF_H1 + SZ_QKV;   // ~1.16 GB

__device__ float g_scratch[TOTAL];

enum { EPI_NONE = 0, EPI_GELU = 1, EPI_QKV = 2, EPI_POS = 3, EPI_CTX = 4 };

__device__ __forceinline__ float to_tf32(float x) {
    uint32_t u;
    asm("cvt.rna.tf32.f32 %0, %1;" : "=r"(u) : "f"(x));
    return __uint_as_float(u);
}

__device__ __forceinline__ void mma_tf32(float (&d)[4], const uint32_t (&a)[4],
                                         const uint32_t (&b)[2]) {
    asm volatile(
        "mma.sync.aligned.m16n8k8.row.col.f32.tf32.tf32.f32 "
        "{%0,%1,%2,%3}, {%4,%5,%6,%7}, {%8,%9}, {%0,%1,%2,%3};"
        : "+f"(d[0]), "+f"(d[1]), "+f"(d[2]), "+f"(d[3])
        : "r"(a[0]), "r"(a[1]), "r"(a[2]), "r"(a[3]), "r"(b[0]), "r"(b[1]));
}

// ---------------------------------------------------------------------------
// Tensor-core GEMM: C = epi(A @ B (+bias)); TB=true computes A @ B^T with both
// operands row-major over K. Batched via blockIdx.z (element strides).
// All tile dims divide the problem dims exactly for every launch below.
//   A smem: m-major [BM][BK+4]   (frag bank = 4*gi+gj, conflict-free)
//   B smem: TB ? n-major [BN][BK+4] : k-major [BK][BN+8]  (conflict-free)
// ---------------------------------------------------------------------------
template<int BM, int BN, int BK, int WM, int WN, bool TB, int EPI>
__global__ __launch_bounds__(WM * WN * 32)
void gemm_tc(const float* __restrict__ Aex, size_t aOff,
             const float* __restrict__ Bex, size_t bOff,
             const float* __restrict__ bias,
             float* __restrict__ Cex, size_t cOff,
             int M, int N, int K,
             size_t aStride, size_t bStride, int bMod, size_t cStride)
{
    constexpr int THREADS = WM * WN * 32;
    constexpr int WTM = BM / WM;          // warp tile m
    constexpr int WTN = BN / WN;          // warp tile n
    constexpr int MT  = WTM / 16;
    constexpr int NT  = WTN / 8;
    constexpr int ASTRIDE = BK + 4;
    constexpr int BSTRIDE = TB ? (BK + 4) : (BN + 8);
    constexpr int BROWS   = TB ? BN : BK;

    __shared__ __align__(16) float As[BM * ASTRIDE];
    __shared__ __align__(16) float Bs[BROWS * BSTRIDE];

    const float* A  = Aex ? Aex : (const float*)g_scratch + aOff;
    const float* Bp = Bex ? Bex : (const float*)g_scratch + bOff;
    float*       C  = Cex ? Cex : g_scratch + cOff;

    const int z = blockIdx.z;
    A  += (size_t)z * aStride;
    Bp += (size_t)(z % bMod) * bStride;

    const int m0   = blockIdx.y * BM;
    const int n0   = blockIdx.x * BN;
    const int tid  = threadIdx.x;
    const int warp = tid >> 5;
    const int lane = tid & 31;
    const int wm = warp % WM, wn = warp / WM;
    const int mBase = wm * WTM, nBase = wn * WTN;
    const int gi = lane >> 2, gj = lane & 3;

    float acc[MT][NT][4];
#pragma unroll
    for (int i = 0; i < MT; i++)
#pragma unroll
        for (int j = 0; j < NT; j++)
#pragma unroll
            for (int r = 0; r < 4; r++) acc[i][j][r] = 0.f;

    for (int k0 = 0; k0 < K; k0 += BK) {
        // --- A tile [BM x BK] -> As[m][k], tf32-rounded, float4 copies ---
        constexpr int LA = (BM * BK) / (4 * THREADS);
#pragma unroll
        for (int r = 0; r < LA; r++) {
            int idx = tid + r * THREADS;
            int row = idx / (BK / 4);
            int kg  = idx % (BK / 4);
            float4 v = *reinterpret_cast<const float4*>(
                &A[(size_t)(m0 + row) * K + k0 + kg * 4]);
            v.x = to_tf32(v.x); v.y = to_tf32(v.y);
            v.z = to_tf32(v.z); v.w = to_tf32(v.w);
            *reinterpret_cast<float4*>(&As[row * ASTRIDE + kg * 4]) = v;
        }
        // --- B tile ---
        if constexpr (TB) {     // B row-major [N,K]: direct copy, n-major smem
            constexpr int LB = (BN * BK) / (4 * THREADS);
#pragma unroll
            for (int r = 0; r < LB; r++) {
                int idx = tid + r * THREADS;
                int row = idx / (BK / 4);
                int kg  = idx % (BK / 4);
                float4 v = *reinterpret_cast<const float4*>(
                    &Bp[(size_t)(n0 + row) * K + k0 + kg * 4]);
                v.x = to_tf32(v.x); v.y = to_tf32(v.y);
                v.z = to_tf32(v.z); v.w = to_tf32(v.w);
                *reinterpret_cast<float4*>(&Bs[row * BSTRIDE + kg * 4]) = v;
            }
        } else {                // B row-major [K,N]: direct copy, k-major smem
            constexpr int LB = (BK * BN) / (4 * THREADS);
#pragma unroll
            for (int r = 0; r < LB; r++) {
                int idx = tid + r * THREADS;
                int kr  = idx / (BN / 4);
                int ng  = idx % (BN / 4);
                float4 v = *reinterpret_cast<const float4*>(
                    &Bp[(size_t)(k0 + kr) * N + n0 + ng * 4]);
                v.x = to_tf32(v.x); v.y = to_tf32(v.y);
                v.z = to_tf32(v.z); v.w = to_tf32(v.w);
                *reinterpret_cast<float4*>(&Bs[kr * BSTRIDE + ng * 4]) = v;
            }
        }
        __syncthreads();

#pragma unroll
        for (int ks = 0; ks < BK / 8; ks++) {
            const int kk = ks * 8;
            uint32_t af[MT][4];
#pragma unroll
            for (int mt = 0; mt < MT; mt++) {
                const int r0 = (mBase + mt * 16 + gi) * ASTRIDE + kk + gj;
                af[mt][0] = __float_as_uint(As[r0]);
                af[mt][1] = __float_as_uint(As[r0 + 8 * ASTRIDE]);
                af[mt][2] = __float_as_uint(As[r0 + 4]);
                af[mt][3] = __float_as_uint(As[r0 + 8 * ASTRIDE + 4]);
            }
            uint32_t bf[NT][2];
#pragma unroll
            for (int nt = 0; nt < NT; nt++) {
                const int col = nBase + nt * 8 + gi;
                if constexpr (TB) {
                    const int b0 = col * BSTRIDE + kk + gj;
                    bf[nt][0] = __float_as_uint(Bs[b0]);
                    bf[nt][1] = __float_as_uint(Bs[b0 + 4]);
                } else {
                    const int b0 = (kk + gj) * BSTRIDE + col;
                    bf[nt][0] = __float_as_uint(Bs[b0]);
                    bf[nt][1] = __float_as_uint(Bs[b0 + 4 * BSTRIDE]);
                }
            }
#pragma unroll
            for (int mt = 0; mt < MT; mt++)
#pragma unroll
                for (int nt = 0; nt < NT; nt++)
                    mma_tf32(acc[mt][nt], af[mt], bf[nt]);
        }
        __syncthreads();
    }

    // --- epilogue: float2 stores from c-fragment pairs ---
#pragma unroll
    for (int mt = 0; mt < MT; mt++) {
#pragma unroll
        for (int nt = 0; nt < NT; nt++) {
#pragma unroll
            for (int half = 0; half < 2; half++) {
                const int m = m0 + mBase + mt * 16 + gi + half * 8;
                const int n = n0 + nBase + nt * 8 + 2 * gj;
                float v0 = acc[mt][nt][half * 2 + 0];
                float v1 = acc[mt][nt][half * 2 + 1];
                if (bias) { v0 += bias[n]; v1 += bias[n + 1]; }
                if constexpr (EPI == EPI_GELU) {
                    v0 = 0.5f * v0 * (1.f + erff(v0 * 0.70710678118654752f));
                    v1 = 0.5f * v1 * (1.f + erff(v1 * 0.70710678118654752f));
                }
                size_t o;
                if constexpr (EPI == EPI_QKV) {        // [B*S,H] -> [B,NH,S,DH]
                    const int bb = m >> 9, s = m & 511, h = n >> 6, d = n & 63;
                    o = ((size_t)(bb * kNH + h) * kS + s) * kDH + d;
                } else if constexpr (EPI == EPI_POS) { // [2P,H] -> [NH,2P,DH]
                    const int h = n >> 6, d = n & 63;
                    o = ((size_t)h * (2 * kP) + m) * kDH + d;
                } else if constexpr (EPI == EPI_CTX) { // [S,DH] per bh -> [B,S,H]
                    const int bb = z / kNH, h = z % kNH;
                    o = ((size_t)bb * kS + m) * kH + h * kDH + n;
                } else {
                    o = (size_t)z * cStride + (size_t)m * N + n;
                }
                *reinterpret_cast<float2*>(&C[o]) = make_float2(v0, v1);
            }
        }
    }
}

// ---------------------------------------------------------------------------
// Assemble: scores = (c2c + gather(c2p_all) + gather(p2c_all)) * scale, mask.
// ---------------------------------------------------------------------------
__global__ void assemble_kernel(const float* __restrict__ mask)
{
    const int z  = blockIdx.z;
    const int i0 = blockIdx.y * 32;
    const int j0 = blockIdx.x * 32;
    const int tx = threadIdx.x;   // 0..31
    const int ty = threadIdx.y;   // 0..7

    __shared__ float p2cT[32][33];
    const float* P2Cz = g_scratch + OFF_P2C + (size_t)z * kS * (2 * kP);
#pragma unroll
    for (int jj = ty; jj < 32; jj += 8) {
        const int j = j0 + jj;
        p2cT[jj][tx] = P2Cz[(size_t)j * (2 * kP) + (j - (i0 + tx) + kP)];
    }
    __syncthreads();

    const float* C2Pz = g_scratch + OFF_C2P + (size_t)z * kS * (2 * kP);
    float* Sz = g_scratch + OFF_S + (size_t)z * kS * kS;
    const float mj = mask[(size_t)(z / kNH) * kS + (j0 + tx)];
#pragma unroll
    for (int ii = ty; ii < 32; ii += 8) {
        const int i = i0 + ii;
        const int j = j0 + tx;
        float s = Sz[(size_t)i * kS + j]
                + C2Pz[(size_t)i * (2 * kP) + (i - j + kP)]
                + p2cT[tx][ii];
        s *= kScale;
        if (mj <= 0.f) s = -1e9f;
        Sz[(size_t)i * kS + j] = s;
    }
}

// ---------------------------------------------------------------------------
// Row softmax over the last axis (512), in place. One block per row.
// ---------------------------------------------------------------------------
__global__ void softmax_kernel()
{
    const size_t row = blockIdx.x;
    float* r = g_scratch + OFF_S + row * kS;
    const int t = threadIdx.x;
    float v0 = r[t], v1 = r[t + 256];

    __shared__ float red[256];
    red[t] = fmaxf(v0, v1);
    __syncthreads();
    for (int s = 128; s > 0; s >>= 1) {
        if (t < s) red[t] = fmaxf(red[t], red[t + s]);
        __syncthreads();
    }
    const float mx = red[0];
    __syncthreads();

    const float e0 = expf(v0 - mx), e1 = expf(v1 - mx);
    red[t] = e0 + e1;
    __syncthreads();
    for (int s = 128; s > 0; s >>= 1) {
        if (t < s) red[t] += red[t + s];
        __syncthreads();
    }
    const float inv = 1.f / red[0];
    r[t] = e0 * inv;
    r[t + 256] = e1 * inv;
}

// ---------------------------------------------------------------------------
// out = LayerNorm(X + Y) * g + b. One block (256 threads) per 768-wide row.
// ---------------------------------------------------------------------------
__global__ void add_ln_kernel(const float* __restrict__ Xex, size_t xOff, size_t yOff,
                              const float* __restrict__ g, const float* __restrict__ bb,
                              float* __restrict__ outEx, size_t outOff)
{
    const float* X = Xex ? Xex : (const float*)g_scratch + xOff;
    const float* Y = (const float*)g_scratch + yOff;
    float* O = outEx ? outEx : g_scratch + outOff;

    const size_t off = (size_t)blockIdx.x * kH;
    const int t = threadIdx.x;
    const float v0 = X[off + t]       + Y[off + t];
    const float v1 = X[off + t + 256] + Y[off + t + 256];
    const float v2 = X[off + t + 512] + Y[off + t + 512];

    __shared__ float red[256];
    red[t] = v0 + v1 + v2;
    __syncthreads();
    for (int s = 128; s > 0; s >>= 1) {
        if (t < s) red[t] += red[t + s];
        __syncthreads();
    }
    const float mean = red[0] * (1.f / 768.f);
    __syncthreads();

    const float d0 = v0 - mean, d1 = v1 - mean, d2 = v2 - mean;
    red[t] = d0 * d0 + d1 * d1 + d2 * d2;
    __syncthreads();
    for (int s = 128; s > 0; s >>= 1) {
        if (t < s) red[t] += red[t + s];
        __syncthreads();
    }
    const float rstd = rsqrtf(red[0] * (1.f / 768.f) + 1e-7f);

    O[off + t]       = d0 * rstd * g[t]       + bb[t];
    O[off + t + 256] = d1 * rstd * g[t + 256] + bb[t + 256];
    O[off + t + 512] = d2 * rstd * g[t + 512] + bb[t + 512];
}

// ---------------------------------------------------------------------------
extern "C" void kernel_launch(void* const* d_in, const int* in_sizes, int n_in,
                              void* d_out, int out_size)
{
    const float* hs  = (const float*)d_in[0];
    const float* am  = (const float*)d_in[1];
    const float* pe  = (const float*)d_in[2];
    const float* Wq  = (const float*)d_in[3];
    const float* bq  = (const float*)d_in[4];
    const float* Wk  = (const float*)d_in[5];
    const float* bk  = (const float*)d_in[6];
    const float* Wv  = (const float*)d_in[7];
    const float* bv  = (const float*)d_in[8];
    const float* Wpk = (const float*)d_in[9];
    const float* Wpq = (const float*)d_in[10];
    const float* Wo  = (const float*)d_in[11];
    const float* bo  = (const float*)d_in[12];
    const float* g1  = (const float*)d_in[13];
    const float* be1 = (const float*)d_in[14];
    const float* W1  = (const float*)d_in[15];
    const float* b1  = (const float*)d_in[16];
    const float* W2  = (const float*)d_in[17];
    const float* b2  = (const float*)d_in[18];
    const float* g2  = (const float*)d_in[19];
    const float* be2 = (const float*)d_in[20];
    float* out = (float*)d_out;

    // --- QKV projections: [8192,768]@[768,768] -> head layout ---
    gemm_tc<128,128,32,4,2,false,EPI_QKV><<<dim3(kH/128, kBS/128, 1), 256>>>(
        hs, 0, Wq, 0, bq, nullptr, OFF_Q, kBS, kH, kH, 0, 0, 1, 0);
    gemm_tc<128,128,32,4,2,false,EPI_QKV><<<dim3(kH/128, kBS/128, 1), 256>>>(
        hs, 0, Wk, 0, bk, nullptr, OFF_K, kBS, kH, kH, 0, 0, 1, 0);
    gemm_tc<128,128,32,4,2,false,EPI_QKV><<<dim3(kH/128, kBS/128, 1), 256>>>(
        hs, 0, Wv, 0, bv, nullptr, OFF_V, kBS, kH, kH, 0, 0, 1, 0);

    // --- relative position projections: [1024,768]@[768,768] -> [NH,2P,DH] ---
    gemm_tc<128,128,32,4,2,false,EPI_POS><<<dim3(kH/128, (2*kP)/128, 1), 256>>>(
        pe, 0, Wpk, 0, nullptr, nullptr, OFF_PK, 2*kP, kH, kH, 0, 0, 1, 0);
    gemm_tc<128,128,32,4,2,false,EPI_POS><<<dim3(kH/128, (2*kP)/128, 1), 256>>>(
        pe, 0, Wpq, 0, nullptr, nullptr, OFF_PQ, 2*kP, kH, kH, 0, 0, 1, 0);

    // --- c2c: per (b,h)  Q[512,64] @ K[512,64]^T ---
    gemm_tc<128,128,32,4,2,true,EPI_NONE><<<dim3(kS/128, kS/128, kBH), 256>>>(
        nullptr, OFF_Q, nullptr, OFF_K, nullptr, nullptr, OFF_S, kS, kS, kDH,
        (size_t)kS*kDH, (size_t)kS*kDH, kBH, (size_t)kS*kS);
    // --- c2p_all: Q @ PK_h^T -> [bh,512,1024] ---
    gemm_tc<128,128,32,4,2,true,EPI_NONE><<<dim3((2*kP)/128, kS/128, kBH), 256>>>(
        nullptr, OFF_Q, nullptr, OFF_PK, nullptr, nullptr, OFF_C2P, kS, 2*kP, kDH,
        (size_t)kS*kDH, (size_t)(2*kP)*kDH, kNH, (size_t)kS*(2*kP));
    // --- p2c_all: K @ PQ_h^T -> [bh,512,1024] ---
    gemm_tc<128,128,32,4,2,true,EPI_NONE><<<dim3((2*kP)/128, kS/128, kBH), 256>>>(
        nullptr, OFF_K, nullptr, OFF_PQ, nullptr, nullptr, OFF_P2C, kS, 2*kP, kDH,
        (size_t)kS*kDH, (size_t)(2*kP)*kDH, kNH, (size_t)kS*(2*kP));

    // --- assemble (+scale, +mask), then softmax, both in place on scores ---
    assemble_kernel<<<dim3(kS/32, kS/32, kBH), dim3(32, 8)>>>(am);
    softmax_kernel<<<kBH * kS, 256>>>();

    // --- ctx = probs @ V -> merged-head [B,S,H] ---
    gemm_tc<128,64,32,4,2,false,EPI_CTX><<<dim3(1, kS/128, kBH), 256>>>(
        nullptr, OFF_S, nullptr, OFF_V, nullptr, nullptr, OFF_CTX, kS, kDH, kS,
        (size_t)kS*kS, (size_t)kS*kDH, kBH, 0);

    // --- output projection + residual LN1 ---
    gemm_tc<128,128,32,4,2,false,EPI_NONE><<<dim3(kH/128, kBS/128, 1), 256>>>(
        nullptr, OFF_CTX, Wo, 0, bo, nullptr, OFF_T1, kBS, kH, kH, 0, 0, 1, 0);
    add_ln_kernel<<<kBS, 256>>>(hs, 0, OFF_T1, g1, be1, nullptr, OFF_H1);

    // --- FFN ---
    gemm_tc<128,128,32,4,2,false,EPI_GELU><<<dim3(kI/128, kBS/128, 1), 256>>>(
        nullptr, OFF_H1, W1, 0, b1, nullptr, OFF_F1, kBS, kI, kH, 0, 0, 1, 0);
    gemm_tc<128,128,32,4,2,false,EPI_NONE><<<dim3(kH/128, kBS/128, 1), 256>>>(
        nullptr, OFF_F1, W2, 0, b2, nullptr, OFF_T1, kBS, kH, kI, 0, 0, 1, 0);
    add_ln_kernel<<<kBS, 256>>>(nullptr, OFF_H1, OFF_T1, g2, be2, out, 0);
}

// round 8
// speedup vs baseline: 3.2230x; 1.2174x over previous
#include <cuda_runtime.h>
#include <math.h>
#include <stdint.h>

// ---------------------------------------------------------------------------
// DeBERTa layer, tf32 tensor-core (mma.sync m16n8k8) + cp.async pipeline.
// B=16 S=512 H=768 NH=12 DH=64 P=512 I=3072.
// scores[i,j] = q_i.k_j + q_i.PK[i-j+P] + k_j.PQ[j-i+P]   (no clipping: |i-j|<=511)
// ---------------------------------------------------------------------------

constexpr int kB  = 16;
constexpr int kS  = 512;
constexpr int kH  = 768;
constexpr int kNH = 12;
constexpr int kDH = 64;
constexpr int kP  = 512;
constexpr int kI  = 3072;
constexpr int kBS = kB * kS;    // 8192
constexpr int kBH = kB * kNH;   // 192
constexpr float kScale = 0.07216878364870322f;  // 1/sqrt(3*64)

// ---- scratch layout (one big __device__ array; no allocations anywhere) ----
constexpr size_t SZ_QKV = (size_t)kBH * kS * kDH;
constexpr size_t SZ_POS = (size_t)kNH * 2 * kP * kDH;
constexpr size_t SZ_S   = (size_t)kBH * kS * kS;
constexpr size_t SZ_CP  = (size_t)kBH * kS * 2 * kP;

constexpr size_t OFF_Q   = 0;
constexpr size_t OFF_K   = OFF_Q + SZ_QKV;
constexpr size_t OFF_V   = OFF_K + SZ_QKV;
constexpr size_t OFF_PK  = OFF_V + SZ_QKV;
constexpr size_t OFF_PQ  = OFF_PK + SZ_POS;
constexpr size_t OFF_S   = OFF_PQ + SZ_POS;   // c2c -> probs (in place)
constexpr size_t OFF_C2P = OFF_S + SZ_S;
constexpr size_t OFF_P2C = OFF_C2P + SZ_CP;
constexpr size_t OFF_CTX = OFF_P2C + SZ_CP;
constexpr size_t OFF_T1  = OFF_CTX + SZ_QKV;
constexpr size_t OFF_H1  = OFF_T1 + SZ_QKV;
constexpr size_t OFF_F1  = OFF_C2P;           // alias: c2p_all dead after fuse
constexpr size_t TOTAL   = OFF_H1 + SZ_QKV;

__device__ float g_scratch[TOTAL];

enum { EPI_NONE = 0, EPI_GELU = 1, EPI_QKV = 2, EPI_POS = 3, EPI_CTX = 4 };

__device__ __forceinline__ uint32_t cvt_tf32(float x) {
    uint32_t u;
    asm("cvt.rna.tf32.f32 %0, %1;" : "=r"(u) : "f"(x));
    return u;
}

__device__ __forceinline__ void mma_tf32(float (&d)[4], const uint32_t (&a)[4],
                                         const uint32_t (&b)[2]) {
    asm volatile(
        "mma.sync.aligned.m16n8k8.row.col.f32.tf32.tf32.f32 "
        "{%0,%1,%2,%3}, {%4,%5,%6,%7}, {%8,%9}, {%0,%1,%2,%3};"
        : "+f"(d[0]), "+f"(d[1]), "+f"(d[2]), "+f"(d[3])
        : "r"(a[0]), "r"(a[1]), "r"(a[2]), "r"(a[3]), "r"(b[0]), "r"(b[1]));
}

__device__ __forceinline__ void cp_async16(uint32_t smem, const void* g) {
    asm volatile("cp.async.cg.shared.global [%0], [%1], 16;" :: "r"(smem), "l"(g));
}
__device__ __forceinline__ void cp_commit() {
    asm volatile("cp.async.commit_group;" ::: "memory");
}
__device__ __forceinline__ void cp_wait1() {
    asm volatile("cp.async.wait_group 1;" ::: "memory");
}

// ---------------------------------------------------------------------------
// Pipelined tensor-core GEMM: C = epi(A @ B (+bias)); TB=true -> A @ B^T with
// both operands row-major over K. 2-stage cp.async double buffering, BK=16.
// DIAG=true: n0 = by*BM + bx*BN (band-limited c2p/p2c tiles).
//   A smem m-major [BM][BK+4], B smem: TB ? n-major [BN][BK+4] : k-major
//   [BK][BN+8] — all fragment reads conflict-free (checked mod-32).
// ---------------------------------------------------------------------------
template<int BM, int BN, int BK, int WM, int WN, bool TB, bool DIAG, int EPI>
__global__ __launch_bounds__(256, 2)
void gemm_tc(const float* __restrict__ Aex, size_t aOff,
             const float* __restrict__ Bex, size_t bOff,
             const float* __restrict__ bias,
             float* __restrict__ Cex, size_t cOff,
             int M, int N, int K,
             size_t aStride, size_t bStride, int bMod, size_t cStride)
{
    static_assert(WM * WN * 32 == 256, "");
    constexpr int WTM = BM / WM;
    constexpr int WTN = BN / WN;
    constexpr int MT  = WTM / 16;
    constexpr int NT  = WTN / 8;
    constexpr int ASTR  = BK + 4;
    constexpr int BSTR  = TB ? (BK + 4) : (BN + 8);
    constexpr int BROWS = TB ? BN : BK;
    constexpr int ASTAGE = BM * ASTR;
    constexpr int BSTAGE = BROWS * BSTR;
    constexpr int LA = (BM * BK) / (4 * 256);
    constexpr int LB = TB ? (BN * BK) / (4 * 256) : (BK * BN) / (4 * 256);

    __shared__ __align__(16) float As[2 * ASTAGE];
    __shared__ __align__(16) float Bs[2 * BSTAGE];

    const float* A  = Aex ? Aex : (const float*)g_scratch + aOff;
    const float* Bp = Bex ? Bex : (const float*)g_scratch + bOff;
    float*       C  = Cex ? Cex : g_scratch + cOff;

    const int z = blockIdx.z;
    A  += (size_t)z * aStride;
    Bp += (size_t)(z % bMod) * bStride;

    const int m0 = blockIdx.y * BM;
    const int n0 = DIAG ? (blockIdx.y * BM + blockIdx.x * BN) : (blockIdx.x * BN);
    const int tid  = threadIdx.x;
    const int warp = tid >> 5;
    const int lane = tid & 31;
    const int wm = warp % WM, wn = warp / WM;
    const int mBase = wm * WTM, nBase = wn * WTN;
    const int gi = lane >> 2, gj = lane & 3;

    const uint32_t sAs = (uint32_t)__cvta_generic_to_shared(As);
    const uint32_t sBs = (uint32_t)__cvta_generic_to_shared(Bs);

    // per-thread load coordinates
    const int aRow = tid >> 2, aKg = tid & 3;               // A & TB-B pattern
    const int bKr = TB ? 0 : (tid / (BN / 4));
    const int bNg = TB ? 0 : (tid % (BN / 4));

    // issue all cp.asyncs for one stage at k-offset kblk
    auto load_stage = [&](int stage, int kblk) {
#pragma unroll
        for (int r = 0; r < LA; r++) {
            const int row = aRow + r * 64;
            cp_async16(sAs + (uint32_t)(stage * ASTAGE + row * ASTR + aKg * 4) * 4,
                       A + (size_t)(m0 + row) * K + kblk + aKg * 4);
        }
        if constexpr (TB) {
#pragma unroll
            for (int r = 0; r < LB; r++) {
                const int row = aRow + r * 64;
                cp_async16(sBs + (uint32_t)(stage * BSTAGE + row * BSTR + aKg * 4) * 4,
                           Bp + (size_t)(n0 + row) * K + kblk + aKg * 4);
            }
        } else {
#pragma unroll
            for (int r = 0; r < LB; r++) {
                const int kr = bKr + r * (1024 / BN);
                cp_async16(sBs + (uint32_t)(stage * BSTAGE + kr * BSTR + bNg * 4) * 4,
                           Bp + (size_t)(kblk + kr) * N + n0 + bNg * 4);
            }
        }
    };

    float acc[MT][NT][4];
#pragma unroll
    for (int i = 0; i < MT; i++)
#pragma unroll
        for (int j = 0; j < NT; j++)
#pragma unroll
            for (int r = 0; r < 4; r++) acc[i][j][r] = 0.f;

    load_stage(0, 0);
    cp_commit();

    const int TSTEPS = K / BK;
    for (int t = 0; t < TSTEPS; t++) {
        const int cur = t & 1;
        if (t + 1 < TSTEPS) load_stage(cur ^ 1, (t + 1) * BK);
        cp_commit();
        cp_wait1();
        __syncthreads();

        const float* Ac = As + cur * ASTAGE;
        const float* Bc = Bs + cur * BSTAGE;
#pragma unroll
        for (int ks = 0; ks < BK / 8; ks++) {
            const int kk = ks * 8;
            uint32_t af[MT][4];
#pragma unroll
            for (int mt = 0; mt < MT; mt++) {
                const int r0 = (mBase + mt * 16 + gi) * ASTR + kk + gj;
                af[mt][0] = cvt_tf32(Ac[r0]);
                af[mt][1] = cvt_tf32(Ac[r0 + 8 * ASTR]);
                af[mt][2] = cvt_tf32(Ac[r0 + 4]);
                af[mt][3] = cvt_tf32(Ac[r0 + 8 * ASTR + 4]);
            }
            uint32_t bf[NT][2];
#pragma unroll
            for (int nt = 0; nt < NT; nt++) {
                const int col = nBase + nt * 8 + gi;
                if constexpr (TB) {
                    const int b0 = col * BSTR + kk + gj;
                    bf[nt][0] = cvt_tf32(Bc[b0]);
                    bf[nt][1] = cvt_tf32(Bc[b0 + 4]);
                } else {
                    const int b0 = (kk + gj) * BSTR + col;
                    bf[nt][0] = cvt_tf32(Bc[b0]);
                    bf[nt][1] = cvt_tf32(Bc[b0 + 4 * BSTR]);
                }
            }
#pragma unroll
            for (int mt = 0; mt < MT; mt++)
#pragma unroll
                for (int nt = 0; nt < NT; nt++)
                    mma_tf32(acc[mt][nt], af[mt], bf[nt]);
        }
        __syncthreads();
    }

    // --- epilogue: float2 stores from c-fragment pairs ---
#pragma unroll
    for (int mt = 0; mt < MT; mt++) {
#pragma unroll
        for (int nt = 0; nt < NT; nt++) {
#pragma unroll
            for (int half = 0; half < 2; half++) {
                const int m = m0 + mBase + mt * 16 + gi + half * 8;
                const int n = n0 + nBase + nt * 8 + 2 * gj;
                float v0 = acc[mt][nt][half * 2 + 0];
                float v1 = acc[mt][nt][half * 2 + 1];
                if (bias) { v0 += bias[n]; v1 += bias[n + 1]; }
                if constexpr (EPI == EPI_GELU) {
                    v0 = 0.5f * v0 * (1.f + erff(v0 * 0.70710678118654752f));
                    v1 = 0.5f * v1 * (1.f + erff(v1 * 0.70710678118654752f));
                }
                size_t o;
                if constexpr (EPI == EPI_QKV) {        // [B*S,H] -> [B,NH,S,DH]
                    const int bb = m >> 9, s = m & 511, h = n >> 6, d = n & 63;
                    o = ((size_t)(bb * kNH + h) * kS + s) * kDH + d;
                } else if constexpr (EPI == EPI_POS) { // [2P,H] -> [NH,2P,DH]
                    const int h = n >> 6, d = n & 63;
                    o = ((size_t)h * (2 * kP) + m) * kDH + d;
                } else if constexpr (EPI == EPI_CTX) { // [S,DH] per bh -> [B,S,H]
                    const int bb = z / kNH, h = z % kNH;
                    o = ((size_t)bb * kS + m) * kH + h * kDH + n;
                } else {
                    o = (size_t)z * cStride + (size_t)m * N + n;
                }
                *reinterpret_cast<float2*>(&C[o]) = make_float2(v0, v1);
            }
        }
    }
}

// ---------------------------------------------------------------------------
// Fused assemble + softmax. One block per (z, 16-row strip): stages the full
// 16x512 score strip in smem (c2c + both gathers + scale + mask), then does
// the row softmax and writes probs. p2c gather staged via transpose tiles.
// ---------------------------------------------------------------------------
__global__ __launch_bounds__(256)
void fused_softmax_kernel(const float* __restrict__ mask)
{
    const int z  = blockIdx.y;
    const int i0 = blockIdx.x * 16;
    const int tid = threadIdx.x;

    __shared__ float sc[16][513];
    __shared__ float p2cT[32][17];
    __shared__ float red[16][17];
    __shared__ float invRow[16];

    const float* P2Cz = g_scratch + OFF_P2C + (size_t)z * kS * (2 * kP);
    const float* C2Pz = g_scratch + OFF_C2P + (size_t)z * kS * (2 * kP);
    float* Sz = g_scratch + OFF_S + (size_t)z * kS * kS;
    const float* mrow = mask + (size_t)(z / kNH) * kS;

    const int jj = tid & 31;
    const int ty = tid >> 5;

    for (int j0 = 0; j0 < kS; j0 += 32) {
        // p2cT[jj][ii] = p2c_all[j, j-i+P]  (reverse-contiguous per j-row)
        {
            int idx = tid;
#pragma unroll
            for (int r = 0; r < 2; r++, idx += 256) {
                const int pj = idx >> 4, pi = idx & 15;
                p2cT[pj][pi] =
                    P2Cz[(size_t)(j0 + pj) * (2 * kP) + (j0 + pj) - (i0 + pi) + kP];
            }
        }
        __syncthreads();
        const int j = j0 + jj;
        const float mj = mrow[j];
#pragma unroll
        for (int ii = ty; ii < 16; ii += 8) {
            const int i = i0 + ii;
            float s = Sz[(size_t)i * kS + j]
                    + C2Pz[(size_t)i * (2 * kP) + (i - j + kP)]
                    + p2cT[jj][ii];
            s *= kScale;
            if (mj <= 0.f) s = -1e9f;
            sc[ii][j] = s;
        }
        __syncthreads();
    }

    // softmax over each of the 16 rows (512 wide); 16 segments x 32 per row
    const int row = tid & 15, sg = tid >> 4;
    float mx = -1e30f;
#pragma unroll
    for (int q = 0; q < 32; q++) mx = fmaxf(mx, sc[row][sg * 32 + q]);
    red[sg][row] = mx;
    __syncthreads();
    mx = red[0][row];
#pragma unroll
    for (int s2 = 1; s2 < 16; s2++) mx = fmaxf(mx, red[s2][row]);
    __syncthreads();
    float sum = 0.f;
#pragma unroll
    for (int q = 0; q < 32; q++) {
        const float e = expf(sc[row][sg * 32 + q] - mx);
        sc[row][sg * 32 + q] = e;
        sum += e;
    }
    red[sg][row] = sum;
    __syncthreads();
    if (tid < 16) {
        float s = 0.f;
#pragma unroll
        for (int s2 = 0; s2 < 16; s2++) s += red[s2][tid];
        invRow[tid] = 1.f / s;
    }
    __syncthreads();
#pragma unroll
    for (int r = 0; r < 32; r++) {
        const int idx = tid + r * 256;
        const int ii = idx >> 9, j = idx & 511;
        Sz[(size_t)(i0 + ii) * kS + j] = sc[ii][j] * invRow[ii];
    }
}

// ---------------------------------------------------------------------------
// out = LayerNorm(X + Y) * g + b. One block (256 threads) per 768-wide row.
// ---------------------------------------------------------------------------
__global__ void add_ln_kernel(const float* __restrict__ Xex, size_t xOff, size_t yOff,
                              const float* __restrict__ g, const float* __restrict__ bb,
                              float* __restrict__ outEx, size_t outOff)
{
    const float* X = Xex ? Xex : (const float*)g_scratch + xOff;
    const float* Y = (const float*)g_scratch + yOff;
    float* O = outEx ? outEx : g_scratch + outOff;

    const size_t off = (size_t)blockIdx.x * kH;
    const int t = threadIdx.x;
    const float v0 = X[off + t]       + Y[off + t];
    const float v1 = X[off + t + 256] + Y[off + t + 256];
    const float v2 = X[off + t + 512] + Y[off + t + 512];

    __shared__ float red[256];
    red[t] = v0 + v1 + v2;
    __syncthreads();
    for (int s = 128; s > 0; s >>= 1) {
        if (t < s) red[t] += red[t + s];
        __syncthreads();
    }
    const float mean = red[0] * (1.f / 768.f);
    __syncthreads();

    const float d0 = v0 - mean, d1 = v1 - mean, d2 = v2 - mean;
    red[t] = d0 * d0 + d1 * d1 + d2 * d2;
    __syncthreads();
    for (int s = 128; s > 0; s >>= 1) {
        if (t < s) red[t] += red[t + s];
        __syncthreads();
    }
    const float rstd = rsqrtf(red[0] * (1.f / 768.f) + 1e-7f);

    O[off + t]       = d0 * rstd * g[t]       + bb[t];
    O[off + t + 256] = d1 * rstd * g[t + 256] + bb[t + 256];
    O[off + t + 512] = d2 * rstd * g[t + 512] + bb[t + 512];
}

// ---------------------------------------------------------------------------
extern "C" void kernel_launch(void* const* d_in, const int* in_sizes, int n_in,
                              void* d_out, int out_size)
{
    const float* hs  = (const float*)d_in[0];
    const float* am  = (const float*)d_in[1];
    const float* pe  = (const float*)d_in[2];
    const float* Wq  = (const float*)d_in[3];
    const float* bq  = (const float*)d_in[4];
    const float* Wk  = (const float*)d_in[5];
    const float* bk  = (const float*)d_in[6];
    const float* Wv  = (const float*)d_in[7];
    const float* bv  = (const float*)d_in[8];
    const float* Wpk = (const float*)d_in[9];
    const float* Wpq = (const float*)d_in[10];
    const float* Wo  = (const float*)d_in[11];
    const float* bo  = (const float*)d_in[12];
    const float* g1  = (const float*)d_in[13];
    const float* be1 = (const float*)d_in[14];
    const float* W1  = (const float*)d_in[15];
    const float* b1  = (const float*)d_in[16];
    const float* W2  = (const float*)d_in[17];
    const float* b2  = (const float*)d_in[18];
    const float* g2  = (const float*)d_in[19];
    const float* be2 = (const float*)d_in[20];
    float* out = (float*)d_out;

    // --- QKV projections: [8192,768]@[768,768] -> head layout ---
    gemm_tc<128,128,16,4,2,false,false,EPI_QKV><<<dim3(kH/128, kBS/128, 1), 256>>>(
        hs, 0, Wq, 0, bq, nullptr, OFF_Q, kBS, kH, kH, 0, 0, 1, 0);
    gemm_tc<128,128,16,4,2,false,false,EPI_QKV><<<dim3(kH/128, kBS/128, 1), 256>>>(
        hs, 0, Wk, 0, bk, nullptr, OFF_K, kBS, kH, kH, 0, 0, 1, 0);
    gemm_tc<128,128,16,4,2,false,false,EPI_QKV><<<dim3(kH/128, kBS/128, 1), 256>>>(
        hs, 0, Wv, 0, bv, nullptr, OFF_V, kBS, kH, kH, 0, 0, 1, 0);

    // --- relative position projections: [1024,768]@[768,768] -> [NH,2P,DH] ---
    gemm_tc<128,128,16,4,2,false,false,EPI_POS><<<dim3(kH/128, (2*kP)/128, 1), 256>>>(
        pe, 0, Wpk, 0, nullptr, nullptr, OFF_PK, 2*kP, kH, kH, 0, 0, 1, 0);
    gemm_tc<128,128,16,4,2,false,false,EPI_POS><<<dim3(kH/128, (2*kP)/128, 1), 256>>>(
        pe, 0, Wpq, 0, nullptr, nullptr, OFF_PQ, 2*kP, kH, kH, 0, 0, 1, 0);

    // --- c2c: per (b,h)  Q[512,64] @ K[512,64]^T ---
    gemm_tc<128,128,16,4,2,true,false,EPI_NONE><<<dim3(kS/128, kS/128, kBH), 256>>>(
        nullptr, OFF_Q, nullptr, OFF_K, nullptr, nullptr, OFF_S, kS, kS, kDH,
        (size_t)kS*kDH, (size_t)kS*kDH, kBH, (size_t)kS*kS);
    // --- c2p_all band: Q @ PK_h^T, only live diagonal tiles (5 per m-tile) ---
    gemm_tc<128,128,16,4,2,true,true,EPI_NONE><<<dim3(5, kS/128, kBH), 256>>>(
        nullptr, OFF_Q, nullptr, OFF_PK, nullptr, nullptr, OFF_C2P, kS, 2*kP, kDH,
        (size_t)kS*kDH, (size_t)(2*kP)*kDH, kNH, (size_t)kS*(2*kP));
    // --- p2c_all band: K @ PQ_h^T ---
    gemm_tc<128,128,16,4,2,true,true,EPI_NONE><<<dim3(5, kS/128, kBH), 256>>>(
        nullptr, OFF_K, nullptr, OFF_PQ, nullptr, nullptr, OFF_P2C, kS, 2*kP, kDH,
        (size_t)kS*kDH, (size_t)(2*kP)*kDH, kNH, (size_t)kS*(2*kP));

    // --- fused assemble (+scale,+mask) + softmax, in place on scores ---
    fused_softmax_kernel<<<dim3(kS/16, kBH), 256>>>(am);

    // --- ctx = probs @ V -> merged-head [B,S,H] ---
    gemm_tc<128,64,16,4,2,false,false,EPI_CTX><<<dim3(1, kS/128, kBH), 256>>>(
        nullptr, OFF_S, nullptr, OFF_V, nullptr, nullptr, OFF_CTX, kS, kDH, kS,
        (size_t)kS*kS, (size_t)kS*kDH, kBH, 0);

    // --- output projection + residual LN1 ---
    gemm_tc<128,128,16,4,2,false,false,EPI_NONE><<<dim3(kH/128, kBS/128, 1), 256>>>(
        nullptr, OFF_CTX, Wo, 0, bo, nullptr, OFF_T1, kBS, kH, kH, 0, 0, 1, 0);
    add_ln_kernel<<<kBS, 256>>>(hs, 0, OFF_T1, g1, be1, nullptr, OFF_H1);

    // --- FFN ---
    gemm_tc<128,128,16,4,2,false,false,EPI_GELU><<<dim3(kI/128, kBS/128, 1), 256>>>(
        nullptr, OFF_H1, W1, 0, b1, nullptr, OFF_F1, kBS, kI, kH, 0, 0, 1, 0);
    gemm_tc<128,128,16,4,2,false,false,EPI_NONE><<<dim3(kH/128, kBS/128, 1), 256>>>(
        nullptr, OFF_F1, W2, 0, b2, nullptr, OFF_T1, kBS, kH, kI, 0, 0, 1, 0);
    add_ln_kernel<<<kBS, 256>>>(nullptr, OFF_H1, OFF_T1, g2, be2, out, 0);
}

// round 9
// speedup vs baseline: 3.3603x; 1.0426x over previous
#include <cuda_runtime.h>
#include <math.h>
#include <stdint.h>

// ---------------------------------------------------------------------------
// DeBERTa layer, tf32 tensor-core (mma.sync m16n8k8) + cp.async pipeline.
// All GEMM operands pre-rounded to tf32 (RNA) once — either by the preconvert
// kernel (external inputs/weights) or in the producing kernel's epilogue — so
// the MMA inner loop issues only LDS + HMMA. Numerics identical to per-tile
// conversion (same rounding of the same values).
// B=16 S=512 H=768 NH=12 DH=64 P=512 I=3072.
// scores[i,j] = q_i.k_j + q_i.PK[i-j+P] + k_j.PQ[j-i+P]  (no clip: |i-j|<=511)
// ---------------------------------------------------------------------------

constexpr int kB  = 16;
constexpr int kS  = 512;
constexpr int kH  = 768;
constexpr int kNH = 12;
constexpr int kDH = 64;
constexpr int kP  = 512;
constexpr int kI  = 3072;
constexpr int kBS = kB * kS;    // 8192
constexpr int kBH = kB * kNH;   // 192
constexpr float kScale = 0.07216878364870322f;  // 1/sqrt(3*64)

constexpr size_t NOBIAS = (size_t)-1;

// ---- scratch layout (one big __device__ array; no allocations anywhere) ----
constexpr size_t SZ_QKV = (size_t)kBH * kS * kDH;        // 6,291,456
constexpr size_t SZ_POS = (size_t)kNH * 2 * kP * kDH;    //   786,432
constexpr size_t SZ_S   = (size_t)kBH * kS * kS;
constexpr size_t SZ_CP  = (size_t)kBH * kS * 2 * kP;
constexpr size_t SZ_W   = (size_t)kH * kH;               //   589,824
constexpr size_t SZ_W1  = (size_t)kH * kI;               // 2,359,296

constexpr size_t OFF_Q    = 0;
constexpr size_t OFF_K    = OFF_Q + SZ_QKV;
constexpr size_t OFF_V    = OFF_K + SZ_QKV;
constexpr size_t OFF_PK   = OFF_V + SZ_QKV;
constexpr size_t OFF_PQ   = OFF_PK + SZ_POS;
constexpr size_t OFF_S    = OFF_PQ + SZ_POS;  // c2c -> probs (in place)
constexpr size_t OFF_C2P  = OFF_S + SZ_S;
constexpr size_t OFF_P2C  = OFF_C2P + SZ_CP;
constexpr size_t OFF_CTX  = OFF_P2C + SZ_CP;
constexpr size_t OFF_T1   = OFF_CTX + SZ_QKV;
constexpr size_t OFF_H1   = OFF_T1 + SZ_QKV;  // fp32 (residual path)
constexpr size_t OFF_H1R  = OFF_H1 + SZ_QKV;  // tf32-rounded (FFN1 A operand)
constexpr size_t OFF_F1   = OFF_C2P;          // alias: c2p dead after softmax
// tf32 copies of external inputs/weights
constexpr size_t OFF_CHS  = OFF_H1R + SZ_QKV;
constexpr size_t OFF_CPE  = OFF_CHS + SZ_QKV;   // hs size == SZ_QKV
constexpr size_t OFF_CWQ  = OFF_CPE + SZ_POS;   // pe size == SZ_POS
constexpr size_t OFF_CWK  = OFF_CWQ + SZ_W;
constexpr size_t OFF_CWV  = OFF_CWK + SZ_W;
constexpr size_t OFF_CWPK = OFF_CWV + SZ_W;
constexpr size_t OFF_CWPQ = OFF_CWPK + SZ_W;
constexpr size_t OFF_CWO  = OFF_CWPQ + SZ_W;
constexpr size_t OFF_CW1  = OFF_CWO + SZ_W;
constexpr size_t OFF_CW2  = OFF_CW1 + SZ_W1;
constexpr size_t OFF_CB   = OFF_CW2 + SZ_W1;    // bq|bk|bv contiguous (fp32)
constexpr size_t TOTAL    = OFF_CB + 3 * kH;

__device__ __align__(256) float g_scratch[TOTAL];

enum { EPI_NONE = 0, EPI_GELU = 1, EPI_QKV = 2, EPI_POS = 3, EPI_CTX = 4 };

__device__ __forceinline__ uint32_t cvt_tf32(float x) {
    uint32_t u;
    asm("cvt.rna.tf32.f32 %0, %1;" : "=r"(u) : "f"(x));
    return u;
}
__device__ __forceinline__ float rnd_tf32(float x) {
    return __uint_as_float(cvt_tf32(x));
}

__device__ __forceinline__ void mma_tf32(float (&d)[4], const uint32_t (&a)[4],
                                         const uint32_t (&b)[2]) {
    asm volatile(
        "mma.sync.aligned.m16n8k8.row.col.f32.tf32.tf32.f32 "
        "{%0,%1,%2,%3}, {%4,%5,%6,%7}, {%8,%9}, {%0,%1,%2,%3};"
        : "+f"(d[0]), "+f"(d[1]), "+f"(d[2]), "+f"(d[3])
        : "r"(a[0]), "r"(a[1]), "r"(a[2]), "r"(a[3]), "r"(b[0]), "r"(b[1]));
}

__device__ __forceinline__ void cp_async16(uint32_t smem, const void* g) {
    asm volatile("cp.async.cg.shared.global [%0], [%1], 16;" :: "r"(smem), "l"(g));
}
__device__ __forceinline__ void cp_commit() {
    asm volatile("cp.async.commit_group;" ::: "memory");
}
__device__ __forceinline__ void cp_wait1() {
    asm volatile("cp.async.wait_group 1;" ::: "memory");
}

// ---------------------------------------------------------------------------
// Pre-round external GEMM operands to tf32 (RNA) into scratch; copy biases
// contiguous (fp32, epilogue-added, never rounded as inputs).
// ---------------------------------------------------------------------------
constexpr size_t F4_HS = SZ_QKV / 4;   // 1,572,864
constexpr size_t F4_PE = SZ_POS / 4;   //   196,608
constexpr size_t F4_W  = SZ_W / 4;     //   147,456
constexpr size_t F4_W1 = SZ_W1 / 4;    //   589,824
constexpr size_t F4_TOTAL = F4_HS + F4_PE + 6 * F4_W + 2 * F4_W1;  // 3,833,856

__global__ __launch_bounds__(256)
void preconvert_kernel(const float* __restrict__ hs, const float* __restrict__ pe,
                       const float* __restrict__ Wq, const float* __restrict__ Wk,
                       const float* __restrict__ Wv, const float* __restrict__ Wpk,
                       const float* __restrict__ Wpq, const float* __restrict__ Wo,
                       const float* __restrict__ W1, const float* __restrict__ W2,
                       const float* __restrict__ bq, const float* __restrict__ bk,
                       const float* __restrict__ bv)
{
    size_t i = (size_t)blockIdx.x * 256 + threadIdx.x;
    if (i < 576) {  // bias copy, 3*768 floats = 576 float4
        float4* cb = reinterpret_cast<float4*>(g_scratch + OFF_CB);
        if (i < 192)      cb[i] = reinterpret_cast<const float4*>(bq)[i];
        else if (i < 384) cb[i] = reinterpret_cast<const float4*>(bk)[i - 192];
        else              cb[i] = reinterpret_cast<const float4*>(bv)[i - 384];
    }
    const float* src; float* dst;
    if (i < F4_HS)                 { src = hs;  dst = g_scratch + OFF_CHS; }
    else if ((i -= F4_HS) < F4_PE) { src = pe;  dst = g_scratch + OFF_CPE; }
    else if ((i -= F4_PE) < F4_W)  { src = Wq;  dst = g_scratch + OFF_CWQ; }
    else if ((i -= F4_W) < F4_W)   { src = Wk;  dst = g_scratch + OFF_CWK; }
    else if ((i -= F4_W) < F4_W)   { src = Wv;  dst = g_scratch + OFF_CWV; }
    else if ((i -= F4_W) < F4_W)   { src = Wpk; dst = g_scratch + OFF_CWPK; }
    else if ((i -= F4_W) < F4_W)   { src = Wpq; dst = g_scratch + OFF_CWPQ; }
    else if ((i -= F4_W) < F4_W)   { src = Wo;  dst = g_scratch + OFF_CWO; }
    else if ((i -= F4_W) < F4_W1)  { src = W1;  dst = g_scratch + OFF_CW1; }
    else { i -= F4_W1;               src = W2;  dst = g_scratch + OFF_CW2; }
    float4 v = reinterpret_cast<const float4*>(src)[i];
    v.x = rnd_tf32(v.x); v.y = rnd_tf32(v.y);
    v.z = rnd_tf32(v.z); v.w = rnd_tf32(v.w);
    reinterpret_cast<float4*>(dst)[i] = v;
}

// ---------------------------------------------------------------------------
// Pipelined tensor-core GEMM: C = epi(A @ B (+bias)); TB=true -> A @ B^T with
// both operands row-major over K. 2-stage cp.async, BK=16. Operands are
// already tf32-rounded -> raw-bit fragment reads, no cvt in the loop.
// DIAG=true: n0 = by*BM + bx*BN (band-limited c2p/p2c tiles).
// RND=true: round outputs to tf32 (outputs that feed another GEMM).
// ---------------------------------------------------------------------------
template<int BM, int BN, int BK, int WM, int WN, bool TB, bool DIAG, int EPI, bool RND>
__global__ __launch_bounds__(256, 2)
void gemm_tc(const float* __restrict__ Aex, size_t aOff,
             const float* __restrict__ Bex, size_t bOff,
             const float* __restrict__ biasEx, size_t biasOff, size_t biasStride,
             float* __restrict__ Cex, size_t cOff,
             int M, int N, int K,
             size_t aStride, size_t bStride, int bMod, size_t cStride)
{
    static_assert(WM * WN * 32 == 256, "");
    constexpr int WTM = BM / WM;
    constexpr int WTN = BN / WN;
    constexpr int MT  = WTM / 16;
    constexpr int NT  = WTN / 8;
    constexpr int ASTR  = BK + 4;
    constexpr int BSTR  = TB ? (BK + 4) : (BN + 8);
    constexpr int BROWS = TB ? BN : BK;
    constexpr int ASTAGE = BM * ASTR;
    constexpr int BSTAGE = BROWS * BSTR;
    constexpr int LA = (BM * BK) / (4 * 256);
    constexpr int LB = TB ? (BN * BK) / (4 * 256) : (BK * BN) / (4 * 256);

    __shared__ __align__(16) float As[2 * ASTAGE];
    __shared__ __align__(16) float Bs[2 * BSTAGE];

    const float* A  = Aex ? Aex : (const float*)g_scratch + aOff;
    const float* Bp = Bex ? Bex : (const float*)g_scratch + bOff;
    float*       C  = Cex ? Cex : g_scratch + cOff;
    const float* bias = biasEx ? biasEx
                      : (biasOff != NOBIAS ? (const float*)g_scratch + biasOff
                                           : nullptr);

    const int z = blockIdx.z;
    A  += (size_t)z * aStride;
    Bp += (size_t)(z % bMod) * bStride;

    const int m0 = blockIdx.y * BM;
    const int n0 = DIAG ? (blockIdx.y * BM + blockIdx.x * BN) : (blockIdx.x * BN);
    const int tid  = threadIdx.x;
    const int warp = tid >> 5;
    const int lane = tid & 31;
    const int wm = warp % WM, wn = warp / WM;
    const int mBase = wm * WTM, nBase = wn * WTN;
    const int gi = lane >> 2, gj = lane & 3;

    const uint32_t sAs = (uint32_t)__cvta_generic_to_shared(As);
    const uint32_t sBs = (uint32_t)__cvta_generic_to_shared(Bs);

    const int aRow = tid >> 2, aKg = tid & 3;   // A & TB-B load pattern
    const int bKr = TB ? 0 : (tid / (BN / 4));
    const int bNg = TB ? 0 : (tid % (BN / 4));

    auto load_stage = [&](int stage, int kblk) {
#pragma unroll
        for (int r = 0; r < LA; r++) {
            const int row = aRow + r * 64;
            cp_async16(sAs + (uint32_t)(stage * ASTAGE + row * ASTR + aKg * 4) * 4,
                       A + (size_t)(m0 + row) * K + kblk + aKg * 4);
        }
        if constexpr (TB) {
#pragma unroll
            for (int r = 0; r < LB; r++) {
                const int row = aRow + r * 64;
                cp_async16(sBs + (uint32_t)(stage * BSTAGE + row * BSTR + aKg * 4) * 4,
                           Bp + (size_t)(n0 + row) * K + kblk + aKg * 4);
            }
        } else {
#pragma unroll
            for (int r = 0; r < LB; r++) {
                const int kr = bKr + r * (1024 / BN);
                cp_async16(sBs + (uint32_t)(stage * BSTAGE + kr * BSTR + bNg * 4) * 4,
                           Bp + (size_t)(kblk + kr) * N + n0 + bNg * 4);
            }
        }
    };

    float acc[MT][NT][4];
#pragma unroll
    for (int i = 0; i < MT; i++)
#pragma unroll
        for (int j = 0; j < NT; j++)
#pragma unroll
            for (int r = 0; r < 4; r++) acc[i][j][r] = 0.f;

    load_stage(0, 0);
    cp_commit();

    const int TSTEPS = K / BK;
    for (int t = 0; t < TSTEPS; t++) {
        const int cur = t & 1;
        if (t + 1 < TSTEPS) load_stage(cur ^ 1, (t + 1) * BK);
        cp_commit();
        cp_wait1();
        __syncthreads();

        const uint32_t* Ac = reinterpret_cast<const uint32_t*>(As) + cur * ASTAGE;
        const uint32_t* Bc = reinterpret_cast<const uint32_t*>(Bs) + cur * BSTAGE;
#pragma unroll
        for (int ks = 0; ks < BK / 8; ks++) {
            const int kk = ks * 8;
            uint32_t af[MT][4];
#pragma unroll
            for (int mt = 0; mt < MT; mt++) {
                const int r0 = (mBase + mt * 16 + gi) * ASTR + kk + gj;
                af[mt][0] = Ac[r0];
                af[mt][1] = Ac[r0 + 8 * ASTR];
                af[mt][2] = Ac[r0 + 4];
                af[mt][3] = Ac[r0 + 8 * ASTR + 4];
            }
            uint32_t bf[NT][2];
#pragma unroll
            for (int nt = 0; nt < NT; nt++) {
                const int col = nBase + nt * 8 + gi;
                if constexpr (TB) {
                    const int b0 = col * BSTR + kk + gj;
                    bf[nt][0] = Bc[b0];
                    bf[nt][1] = Bc[b0 + 4];
                } else {
                    const int b0 = (kk + gj) * BSTR + col;
                    bf[nt][0] = Bc[b0];
                    bf[nt][1] = Bc[b0 + 4 * BSTR];
                }
            }
#pragma unroll
            for (int mt = 0; mt < MT; mt++)
#pragma unroll
                for (int nt = 0; nt < NT; nt++)
                    mma_tf32(acc[mt][nt], af[mt], bf[nt]);
        }
        __syncthreads();
    }

    // --- epilogue: float2 stores from c-fragment pairs ---
#pragma unroll
    for (int mt = 0; mt < MT; mt++) {
#pragma unroll
        for (int nt = 0; nt < NT; nt++) {
#pragma unroll
            for (int half = 0; half < 2; half++) {
                const int m = m0 + mBase + mt * 16 + gi + half * 8;
                const int n = n0 + nBase + nt * 8 + 2 * gj;
                float v0 = acc[mt][nt][half * 2 + 0];
                float v1 = acc[mt][nt][half * 2 + 1];
                if (bias) {
                    const float* bz = bias + (size_t)(z % bMod) * biasStride;
                    v0 += bz[n]; v1 += bz[n + 1];
                }
                if constexpr (EPI == EPI_GELU) {
                    v0 = 0.5f * v0 * (1.f + erff(v0 * 0.70710678118654752f));
                    v1 = 0.5f * v1 * (1.f + erff(v1 * 0.70710678118654752f));
                }
                if constexpr (RND) { v0 = rnd_tf32(v0); v1 = rnd_tf32(v1); }
                size_t o;
                if constexpr (EPI == EPI_QKV) {        // [B*S,H] -> [B,NH,S,DH]
                    const int bb = m >> 9, s = m & 511, h = n >> 6, d = n & 63;
                    o = ((size_t)(bb * kNH + h) * kS + s) * kDH + d
                      + (size_t)z * cStride;           // z selects Q/K/V region
                } else if constexpr (EPI == EPI_POS) { // [2P,H] -> [NH,2P,DH]
                    const int h = n >> 6, d = n & 63;
                    o = ((size_t)h * (2 * kP) + m) * kDH + d
                      + (size_t)z * cStride;           // z selects PK/PQ region
                } else if constexpr (EPI == EPI_CTX) { // [S,DH] per bh -> [B,S,H]
                    const int bb = z / kNH, h = z % kNH;
                    o = ((size_t)bb * kS + m) * kH + h * kDH + n;
                } else {
                    o = (size_t)z * cStride + (size_t)m * N + n;
                }
                *reinterpret_cast<float2*>(&C[o]) = make_float2(v0, v1);
            }
        }
    }
}

// ---------------------------------------------------------------------------
// Fused assemble + softmax. One block per (z, 16-row strip). Probs written
// tf32-rounded (they feed the attn.V GEMM).
// ---------------------------------------------------------------------------
__global__ __launch_bounds__(256)
void fused_softmax_kernel(const float* __restrict__ mask)
{
    const int z  = blockIdx.y;
    const int i0 = blockIdx.x * 16;
    const int tid = threadIdx.x;

    __shared__ float sc[16][513];
    __shared__ float p2cT[32][17];
    __shared__ float red[16][17];
    __shared__ float invRow[16];

    const float* P2Cz = g_scratch + OFF_P2C + (size_t)z * kS * (2 * kP);
    const float* C2Pz = g_scratch + OFF_C2P + (size_t)z * kS * (2 * kP);
    float* Sz = g_scratch + OFF_S + (size_t)z * kS * kS;
    const float* mrow = mask + (size_t)(z / kNH) * kS;

    const int jj = tid & 31;
    const int ty = tid >> 5;

    for (int j0 = 0; j0 < kS; j0 += 32) {
        {
            int idx = tid;
#pragma unroll
            for (int r = 0; r < 2; r++, idx += 256) {
                const int pj = idx >> 4, pi = idx & 15;
                p2cT[pj][pi] =
                    P2Cz[(size_t)(j0 + pj) * (2 * kP) + (j0 + pj) - (i0 + pi) + kP];
            }
        }
        __syncthreads();
        const int j = j0 + jj;
        const float mj = mrow[j];
#pragma unroll
        for (int ii = ty; ii < 16; ii += 8) {
            const int i = i0 + ii;
            float s = Sz[(size_t)i * kS + j]
                    + C2Pz[(size_t)i * (2 * kP) + (i - j + kP)]
                    + p2cT[jj][ii];
            s *= kScale;
            if (mj <= 0.f) s = -1e9f;
            sc[ii][j] = s;
        }
        __syncthreads();
    }

    const int row = tid & 15, sg = tid >> 4;
    float mx = -1e30f;
#pragma unroll
    for (int q = 0; q < 32; q++) mx = fmaxf(mx, sc[row][sg * 32 + q]);
    red[sg][row] = mx;
    __syncthreads();
    mx = red[0][row];
#pragma unroll
    for (int s2 = 1; s2 < 16; s2++) mx = fmaxf(mx, red[s2][row]);
    __syncthreads();
    float sum = 0.f;
#pragma unroll
    for (int q = 0; q < 32; q++) {
        const float e = expf(sc[row][sg * 32 + q] - mx);
        sc[row][sg * 32 + q] = e;
        sum += e;
    }
    red[sg][row] = sum;
    __syncthreads();
    if (tid < 16) {
        float s = 0.f;
#pragma unroll
        for (int s2 = 0; s2 < 16; s2++) s += red[s2][tid];
        invRow[tid] = 1.f / s;
    }
    __syncthreads();
#pragma unroll
    for (int r = 0; r < 32; r++) {
        const int idx = tid + r * 256;
        const int ii = idx >> 9, j = idx & 511;
        Sz[(size_t)(i0 + ii) * kS + j] = rnd_tf32(sc[ii][j] * invRow[ii]);
    }
}

// ---------------------------------------------------------------------------
// out = LayerNorm(X + Y) * g + b; optionally also writes a tf32-rounded copy
// (for the GEMM that consumes it) while keeping the fp32 original.
// ---------------------------------------------------------------------------
__global__ void add_ln_kernel(const float* __restrict__ Xex, size_t xOff, size_t yOff,
                              const float* __restrict__ g, const float* __restrict__ bb,
                              float* __restrict__ outEx, size_t outOff,
                              int makeRounded, size_t rOff)
{
    const float* X = Xex ? Xex : (const float*)g_scratch + xOff;
    const float* Y = (const float*)g_scratch + yOff;
    float* O = outEx ? outEx : g_scratch + outOff;

    const size_t off = (size_t)blockIdx.x * kH;
    const int t = threadIdx.x;
    const float v0 = X[off + t]       + Y[off + t];
    const float v1 = X[off + t + 256] + Y[off + t + 256];
    const float v2 = X[off + t + 512] + Y[off + t + 512];

    __shared__ float red[256];
    red[t] = v0 + v1 + v2;
    __syncthreads();
    for (int s = 128; s > 0; s >>= 1) {
        if (t < s) red[t] += red[t + s];
        __syncthreads();
    }
    const float mean = red[0] * (1.f / 768.f);
    __syncthreads();

    const float d0 = v0 - mean, d1 = v1 - mean, d2 = v2 - mean;
    red[t] = d0 * d0 + d1 * d1 + d2 * d2;
    __syncthreads();
    for (int s = 128; s > 0; s >>= 1) {
        if (t < s) red[t] += red[t + s];
        __syncthreads();
    }
    const float rstd = rsqrtf(red[0] * (1.f / 768.f) + 1e-7f);

    const float o0 = d0 * rstd * g[t]       + bb[t];
    const float o1 = d1 * rstd * g[t + 256] + bb[t + 256];
    const float o2 = d2 * rstd * g[t + 512] + bb[t + 512];
    O[off + t]       = o0;
    O[off + t + 256] = o1;
    O[off + t + 512] = o2;
    if (makeRounded) {
        float* R = g_scratch + rOff;
        R[off + t]       = rnd_tf32(o0);
        R[off + t + 256] = rnd_tf32(o1);
        R[off + t + 512] = rnd_tf32(o2);
    }
}

// ---------------------------------------------------------------------------
extern "C" void kernel_launch(void* const* d_in, const int* in_sizes, int n_in,
                              void* d_out, int out_size)
{
    const float* hs  = (const float*)d_in[0];
    const float* am  = (const float*)d_in[1];
    const float* pe  = (const float*)d_in[2];
    const float* Wq  = (const float*)d_in[3];
    const float* bq  = (const float*)d_in[4];
    const float* Wk  = (const float*)d_in[5];
    const float* bk  = (const float*)d_in[6];
    const float* Wv  = (const float*)d_in[7];
    const float* bv  = (const float*)d_in[8];
    const float* Wpk = (const float*)d_in[9];
    const float* Wpq = (const float*)d_in[10];
    const float* Wo  = (const float*)d_in[11];
    const float* bo  = (const float*)d_in[12];
    const float* g1  = (const float*)d_in[13];
    const float* be1 = (const float*)d_in[14];
    const float* W1  = (const float*)d_in[15];
    const float* b1  = (const float*)d_in[16];
    const float* W2  = (const float*)d_in[17];
    const float* b2  = (const float*)d_in[18];
    const float* g2  = (const float*)d_in[19];
    const float* be2 = (const float*)d_in[20];
    float* out = (float*)d_out;

    // --- pre-round all external GEMM operands to tf32 (once) ---
    preconvert_kernel<<<(int)(F4_TOTAL / 256), 256>>>(
        hs, pe, Wq, Wk, Wv, Wpk, Wpq, Wo, W1, W2, bq, bk, bv);

    // --- merged QKV: z in {0,1,2} selects weight/bias/output region ---
    gemm_tc<128,128,16,4,2,false,false,EPI_QKV,true><<<dim3(kH/128, kBS/128, 3), 256>>>(
        nullptr, OFF_CHS, nullptr, OFF_CWQ, nullptr, OFF_CB, kH,
        nullptr, OFF_Q, kBS, kH, kH, 0, SZ_W, 3, SZ_QKV);

    // --- merged position projections: z in {0,1} -> PK/PQ ---
    gemm_tc<128,128,16,4,2,false,false,EPI_POS,true><<<dim3(kH/128, (2*kP)/128, 2), 256>>>(
        nullptr, OFF_CPE, nullptr, OFF_CWPK, nullptr, NOBIAS, 0,
        nullptr, OFF_PK, 2*kP, kH, kH, 0, SZ_W, 2, SZ_POS);

    // --- c2c: per (b,h)  Q[512,64] @ K[512,64]^T (fp32 out, feeds softmax) ---
    gemm_tc<128,128,16,4,2,true,false,EPI_NONE,false><<<dim3(kS/128, kS/128, kBH), 256>>>(
        nullptr, OFF_Q, nullptr, OFF_K, nullptr, NOBIAS, 0,
        nullptr, OFF_S, kS, kS, kDH,
        (size_t)kS*kDH, (size_t)kS*kDH, kBH, (size_t)kS*kS);
    // --- c2p_all band: Q @ PK_h^T, live diagonal tiles only ---
    gemm_tc<128,128,16,4,2,true,true,EPI_NONE,false><<<dim3(5, kS/128, kBH), 256>>>(
        nullptr, OFF_Q, nullptr, OFF_PK, nullptr, NOBIAS, 0,
        nullptr, OFF_C2P, kS, 2*kP, kDH,
        (size_t)kS*kDH, (size_t)(2*kP)*kDH, kNH, (size_t)kS*(2*kP));
    // --- p2c_all band: K @ PQ_h^T ---
    gemm_tc<128,128,16,4,2,true,true,EPI_NONE,false><<<dim3(5, kS/128, kBH), 256>>>(
        nullptr, OFF_K, nullptr, OFF_PQ, nullptr, NOBIAS, 0,
        nullptr, OFF_P2C, kS, 2*kP, kDH,
        (size_t)kS*kDH, (size_t)(2*kP)*kDH, kNH, (size_t)kS*(2*kP));

    // --- fused assemble (+scale,+mask) + softmax; probs tf32-rounded ---
    fused_softmax_kernel<<<dim3(kS/16, kBH), 256>>>(am);

    // --- ctx = probs @ V -> merged-head [B,S,H], tf32-rounded ---
    gemm_tc<128,64,16,4,2,false,false,EPI_CTX,true><<<dim3(1, kS/128, kBH), 256>>>(
        nullptr, OFF_S, nullptr, OFF_V, nullptr, NOBIAS, 0,
        nullptr, OFF_CTX, kS, kDH, kS,
        (size_t)kS*kS, (size_t)kS*kDH, kBH, 0);

    // --- output projection + residual LN1 (H1 fp32 + tf32 copy for FFN1) ---
    gemm_tc<128,128,16,4,2,false,false,EPI_NONE,false><<<dim3(kH/128, kBS/128, 1), 256>>>(
        nullptr, OFF_CTX, nullptr, OFF_CWO, bo, NOBIAS, 0,
        nullptr, OFF_T1, kBS, kH, kH, 0, 0, 1, 0);
    add_ln_kernel<<<kBS, 256>>>(hs, 0, OFF_T1, g1, be1, nullptr, OFF_H1, 1, OFF_H1R);

    // --- FFN ---
    gemm_tc<128,128,16,4,2,false,false,EPI_GELU,true><<<dim3(kI/128, kBS/128, 1), 256>>>(
        nullptr, OFF_H1R, nullptr, OFF_CW1, b1, NOBIAS, 0,
        nullptr, OFF_F1, kBS, kI, kH, 0, 0, 1, 0);
    gemm_tc<128,128,16,4,2,false,false,EPI_NONE,false><<<dim3(kH/128, kBS/128, 1), 256>>>(
        nullptr, OFF_F1, nullptr, OFF_CW2, b2, NOBIAS, 0,
        nullptr, OFF_T1, kBS, kH, kI, 0, 0, 1, 0);
    add_ln_kernel<<<kBS, 256>>>(nullptr, OFF_H1, OFF_T1, g2, be2, out, 0, 0, 0);
}

// round 10
// speedup vs baseline: 3.6274x; 1.0795x over previous
#include <cuda_runtime.h>
#include <math.h>
#include <stdint.h>

// ---------------------------------------------------------------------------
// DeBERTa layer, tf32 tensor-core (mma.sync m16n8k8), 3-stage cp.async ring
// with one barrier per k-tile, dynamic smem, score assembly fused into the
// c2c GEMM epilogue. All GEMM operands pre-rounded to tf32 (RNA) once.
// B=16 S=512 H=768 NH=12 DH=64 P=512 I=3072.
// scores[i,j] = q_i.k_j + q_i.PK[i-j+P] + k_j.PQ[j-i+P]  (no clip: |i-j|<=511)
// ---------------------------------------------------------------------------

constexpr int kB  = 16;
constexpr int kS  = 512;
constexpr int kH  = 768;
constexpr int kNH = 12;
constexpr int kDH = 64;
constexpr int kP  = 512;
constexpr int kI  = 3072;
constexpr int kBS = kB * kS;    // 8192
constexpr int kBH = kB * kNH;   // 192
constexpr float kScale = 0.07216878364870322f;  // 1/sqrt(3*64)

constexpr size_t NOBIAS = (size_t)-1;

// ---- scratch layout ----
constexpr size_t SZ_QKV = (size_t)kBH * kS * kDH;
constexpr size_t SZ_POS = (size_t)kNH * 2 * kP * kDH;
constexpr size_t SZ_S   = (size_t)kBH * kS * kS;
constexpr size_t SZ_CP  = (size_t)kBH * kS * 2 * kP;
constexpr size_t SZ_W   = (size_t)kH * kH;
constexpr size_t SZ_W1  = (size_t)kH * kI;

constexpr size_t OFF_Q    = 0;
constexpr size_t OFF_K    = OFF_Q + SZ_QKV;
constexpr size_t OFF_V    = OFF_K + SZ_QKV;
constexpr size_t OFF_PK   = OFF_V + SZ_QKV;
constexpr size_t OFF_PQ   = OFF_PK + SZ_POS;
constexpr size_t OFF_S    = OFF_PQ + SZ_POS;  // scores -> probs (in place)
constexpr size_t OFF_C2P  = OFF_S + SZ_S;
constexpr size_t OFF_P2C  = OFF_C2P + SZ_CP;
constexpr size_t OFF_CTX  = OFF_P2C + SZ_CP;
constexpr size_t OFF_T1   = OFF_CTX + SZ_QKV;
constexpr size_t OFF_H1   = OFF_T1 + SZ_QKV;  // fp32 (residual path)
constexpr size_t OFF_H1R  = OFF_H1 + SZ_QKV;  // tf32-rounded (FFN1 A operand)
constexpr size_t OFF_F1   = OFF_C2P;          // alias: c2p dead after scores
constexpr size_t OFF_CHS  = OFF_H1R + SZ_QKV;
constexpr size_t OFF_CPE  = OFF_CHS + SZ_QKV;
constexpr size_t OFF_CWQ  = OFF_CPE + SZ_POS;
constexpr size_t OFF_CWK  = OFF_CWQ + SZ_W;
constexpr size_t OFF_CWV  = OFF_CWK + SZ_W;
constexpr size_t OFF_CWPK = OFF_CWV + SZ_W;
constexpr size_t OFF_CWPQ = OFF_CWPK + SZ_W;
constexpr size_t OFF_CWO  = OFF_CWPQ + SZ_W;
constexpr size_t OFF_CW1  = OFF_CWO + SZ_W;
constexpr size_t OFF_CW2  = OFF_CW1 + SZ_W1;
constexpr size_t OFF_CB   = OFF_CW2 + SZ_W1;
constexpr size_t TOTAL    = OFF_CB + 3 * kH;

__device__ __align__(256) float g_scratch[TOTAL];

enum { EPI_NONE = 0, EPI_GELU = 1, EPI_QKV = 2, EPI_POS = 3, EPI_CTX = 4,
       EPI_SCORE = 5 };

__device__ __forceinline__ uint32_t cvt_tf32(float x) {
    uint32_t u;
    asm("cvt.rna.tf32.f32 %0, %1;" : "=r"(u) : "f"(x));
    return u;
}
__device__ __forceinline__ float rnd_tf32(float x) {
    return __uint_as_float(cvt_tf32(x));
}

__device__ __forceinline__ void mma_tf32(float (&d)[4], const uint32_t (&a)[4],
                                         const uint32_t (&b)[2]) {
    asm volatile(
        "mma.sync.aligned.m16n8k8.row.col.f32.tf32.tf32.f32 "
        "{%0,%1,%2,%3}, {%4,%5,%6,%7}, {%8,%9}, {%0,%1,%2,%3};"
        : "+f"(d[0]), "+f"(d[1]), "+f"(d[2]), "+f"(d[3])
        : "r"(a[0]), "r"(a[1]), "r"(a[2]), "r"(a[3]), "r"(b[0]), "r"(b[1]));
}

__device__ __forceinline__ void cp_async16(uint32_t smem, const void* g) {
    asm volatile("cp.async.cg.shared.global [%0], [%1], 16;" :: "r"(smem), "l"(g));
}
__device__ __forceinline__ void cp_commit() {
    asm volatile("cp.async.commit_group;" ::: "memory");
}
__device__ __forceinline__ void cp_wait1() {
    asm volatile("cp.async.wait_group 1;" ::: "memory");
}

// ---------------------------------------------------------------------------
// Pre-round external GEMM operands to tf32 (RNA) into scratch.
// ---------------------------------------------------------------------------
constexpr size_t F4_HS = SZ_QKV / 4;
constexpr size_t F4_PE = SZ_POS / 4;
constexpr size_t F4_W  = SZ_W / 4;
constexpr size_t F4_W1 = SZ_W1 / 4;
constexpr size_t F4_TOTAL = F4_HS + F4_PE + 6 * F4_W + 2 * F4_W1;

__global__ __launch_bounds__(256)
void preconvert_kernel(const float* __restrict__ hs, const float* __restrict__ pe,
                       const float* __restrict__ Wq, const float* __restrict__ Wk,
                       const float* __restrict__ Wv, const float* __restrict__ Wpk,
                       const float* __restrict__ Wpq, const float* __restrict__ Wo,
                       const float* __restrict__ W1, const float* __restrict__ W2,
                       const float* __restrict__ bq, const float* __restrict__ bk,
                       const float* __restrict__ bv)
{
    size_t i = (size_t)blockIdx.x * 256 + threadIdx.x;
    if (i < 576) {
        float4* cb = reinterpret_cast<float4*>(g_scratch + OFF_CB);
        if (i < 192)      cb[i] = reinterpret_cast<const float4*>(bq)[i];
        else if (i < 384) cb[i] = reinterpret_cast<const float4*>(bk)[i - 192];
        else              cb[i] = reinterpret_cast<const float4*>(bv)[i - 384];
    }
    const float* src; float* dst;
    if (i < F4_HS)                 { src = hs;  dst = g_scratch + OFF_CHS; }
    else if ((i -= F4_HS) < F4_PE) { src = pe;  dst = g_scratch + OFF_CPE; }
    else if ((i -= F4_PE) < F4_W)  { src = Wq;  dst = g_scratch + OFF_CWQ; }
    else if ((i -= F4_W) < F4_W)   { src = Wk;  dst = g_scratch + OFF_CWK; }
    else if ((i -= F4_W) < F4_W)   { src = Wv;  dst = g_scratch + OFF_CWV; }
    else if ((i -= F4_W) < F4_W)   { src = Wpk; dst = g_scratch + OFF_CWPK; }
    else if ((i -= F4_W) < F4_W)   { src = Wpq; dst = g_scratch + OFF_CWPQ; }
    else if ((i -= F4_W) < F4_W)   { src = Wo;  dst = g_scratch + OFF_CWO; }
    else if ((i -= F4_W) < F4_W1)  { src = W1;  dst = g_scratch + OFF_CW1; }
    else { i -= F4_W1;               src = W2;  dst = g_scratch + OFF_CW2; }
    float4 v = reinterpret_cast<const float4*>(src)[i];
    v.x = rnd_tf32(v.x); v.y = rnd_tf32(v.y);
    v.z = rnd_tf32(v.z); v.w = rnd_tf32(v.w);
    reinterpret_cast<float4*>(dst)[i] = v;
}

// ---------------------------------------------------------------------------
// Pipelined tensor-core GEMM. BK=32, 3-stage cp.async ring, ONE barrier per
// k-tile (loads for stage t+2 are issued after the barrier, into a buffer
// distinct from the two being read). Dynamic smem.
// TB: A @ B^T, both row-major over K.  DIAG: n0 = by*BM + bx*BN (band tiles).
// RND: round outputs to tf32. EPI_SCORE: add gathered c2p/p2c + scale + mask
// (biasEx carries the attention mask).
// ---------------------------------------------------------------------------
template<int BM, int BN, int BK, int WM, int WN, bool TB, bool DIAG, int EPI, bool RND>
__global__ __launch_bounds__(256, 2)
void gemm_tc(const float* __restrict__ Aex, size_t aOff,
             const float* __restrict__ Bex, size_t bOff,
             const float* __restrict__ biasEx, size_t biasOff, size_t biasStride,
             float* __restrict__ Cex, size_t cOff,
             int M, int N, int K,
             size_t aStride, size_t bStride, int bMod, size_t cStride)
{
    static_assert(WM * WN * 32 == 256, "");
    constexpr int WTM = BM / WM;
    constexpr int WTN = BN / WN;
    constexpr int MT  = WTM / 16;
    constexpr int NT  = WTN / 8;
    constexpr int ASTR  = BK + 4;
    constexpr int BSTR  = TB ? (BK + 4) : (BN + 8);
    constexpr int BROWS = TB ? BN : BK;
    constexpr int ASTAGE = BM * ASTR;
    constexpr int BSTAGE = BROWS * BSTR;
    constexpr int LA = (BM * BK) / (4 * 256);
    constexpr int LB = TB ? (BN * BK) / (4 * 256) : (BK * BN) / (4 * 256);

    extern __shared__ __align__(16) float dsm[];
    float* As = dsm;
    float* Bs = dsm + 3 * ASTAGE;

    const float* A  = Aex ? Aex : (const float*)g_scratch + aOff;
    const float* Bp = Bex ? Bex : (const float*)g_scratch + bOff;
    float*       C  = Cex ? Cex : g_scratch + cOff;
    const float* bias = biasEx ? biasEx
                      : (biasOff != NOBIAS ? (const float*)g_scratch + biasOff
                                           : nullptr);

    const int z = blockIdx.z;
    A  += (size_t)z * aStride;
    Bp += (size_t)(z % bMod) * bStride;

    const int m0 = blockIdx.y * BM;
    const int n0 = DIAG ? (blockIdx.y * BM + blockIdx.x * BN) : (blockIdx.x * BN);
    const int tid  = threadIdx.x;
    const int warp = tid >> 5;
    const int lane = tid & 31;
    const int wm = warp % WM, wn = warp / WM;
    const int mBase = wm * WTM, nBase = wn * WTN;
    const int gi = lane >> 2, gj = lane & 3;

    const uint32_t sAs = (uint32_t)__cvta_generic_to_shared(As);
    const uint32_t sBs = (uint32_t)__cvta_generic_to_shared(Bs);

    const int aRow = tid >> 3, aKg = tid & 7;                 // BK=32: 8 f4/row
    const int bKr = TB ? 0 : (tid / (BN / 4));
    const int bNg = TB ? 0 : (tid % (BN / 4));

    auto load_stage = [&](int stage, int kblk) {
#pragma unroll
        for (int r = 0; r < LA; r++) {
            const int row = aRow + r * 32;
            cp_async16(sAs + (uint32_t)(stage * ASTAGE + row * ASTR + aKg * 4) * 4,
                       A + (size_t)(m0 + row) * K + kblk + aKg * 4);
        }
        if constexpr (TB) {
#pragma unroll
            for (int r = 0; r < LB; r++) {
                const int row = aRow + r * 32;
                cp_async16(sBs + (uint32_t)(stage * BSTAGE + row * BSTR + aKg * 4) * 4,
                           Bp + (size_t)(n0 + row) * K + kblk + aKg * 4);
            }
        } else {
#pragma unroll
            for (int r = 0; r < LB; r++) {
                const int kr = bKr + r * (1024 / BN);
                cp_async16(sBs + (uint32_t)(stage * BSTAGE + kr * BSTR + bNg * 4) * 4,
                           Bp + (size_t)(kblk + kr) * N + n0 + bNg * 4);
            }
        }
    };

    float acc[MT][NT][4];
#pragma unroll
    for (int i = 0; i < MT; i++)
#pragma unroll
        for (int j = 0; j < NT; j++)
#pragma unroll
            for (int r = 0; r < 4; r++) acc[i][j][r] = 0.f;

    load_stage(0, 0);
    cp_commit();
    load_stage(1, BK);
    cp_commit();

    const int TSTEPS = K / BK;
    for (int t = 0; t < TSTEPS; t++) {
        cp_wait1();            // stage t complete (<=1 newer group pending)
        __syncthreads();       // all warps past reads of stage (t+2)%3==(t-1)%3
        if (t + 2 < TSTEPS) load_stage((t + 2) % 3, (t + 2) * BK);
        cp_commit();

        const int cur = t % 3;
        const uint32_t* Ac = reinterpret_cast<const uint32_t*>(As) + cur * ASTAGE;
        const uint32_t* Bc = reinterpret_cast<const uint32_t*>(Bs) + cur * BSTAGE;
#pragma unroll
        for (int ks = 0; ks < BK / 8; ks++) {
            const int kk = ks * 8;
            uint32_t af[MT][4];
#pragma unroll
            for (int mt = 0; mt < MT; mt++) {
                const int r0 = (mBase + mt * 16 + gi) * ASTR + kk + gj;
                af[mt][0] = Ac[r0];
                af[mt][1] = Ac[r0 + 8 * ASTR];
                af[mt][2] = Ac[r0 + 4];
                af[mt][3] = Ac[r0 + 8 * ASTR + 4];
            }
            uint32_t bf[NT][2];
#pragma unroll
            for (int nt = 0; nt < NT; nt++) {
                const int col = nBase + nt * 8 + gi;
                if constexpr (TB) {
                    const int b0 = col * BSTR + kk + gj;
                    bf[nt][0] = Bc[b0];
                    bf[nt][1] = Bc[b0 + 4];
                } else {
                    const int b0 = (kk + gj) * BSTR + col;
                    bf[nt][0] = Bc[b0];
                    bf[nt][1] = Bc[b0 + 4 * BSTR];
                }
            }
#pragma unroll
            for (int mt = 0; mt < MT; mt++)
#pragma unroll
                for (int nt = 0; nt < NT; nt++)
                    mma_tf32(acc[mt][nt], af[mt], bf[nt]);
        }
    }

    if constexpr (EPI == EPI_SCORE) {
        // --- fused score assembly: + p2c gather + c2p gather, scale, mask ---
        constexpr int PSTR = 132;   // 132 % 32 == 4 -> conflict-light reads
        const float* P2Cz = (const float*)g_scratch + OFF_P2C
                          + (size_t)z * kS * (2 * kP);
        const float* C2Pz = (const float*)g_scratch + OFF_C2P
                          + (size_t)z * kS * (2 * kP);
        __syncthreads();   // mainloop reads done before smem reuse
        // stage p2cS[jl][il] = p2c_all[n0+jl][(n0+jl)-(m0+il)+P]
#pragma unroll
        for (int r = 0; r < 64; r++) {
            const int idx = tid + r * 256;
            const int jl = idx >> 7, il = idx & 127;
            dsm[jl * PSTR + il] =
                P2Cz[(size_t)(n0 + jl) * (2 * kP) + (n0 + jl) - (m0 + il) + kP];
        }
        __syncthreads();
#pragma unroll
        for (int mt = 0; mt < MT; mt++)
#pragma unroll
            for (int nt = 0; nt < NT; nt++)
#pragma unroll
                for (int half = 0; half < 2; half++) {
                    const int il = mBase + mt * 16 + gi + half * 8;
                    const int jl = nBase + nt * 8 + 2 * gj;
                    acc[mt][nt][half * 2 + 0] += dsm[jl * PSTR + il];
                    acc[mt][nt][half * 2 + 1] += dsm[(jl + 1) * PSTR + il];
                }
        __syncthreads();
        // stage c2pS[il][jl] = c2p_all[m0+il][(m0+il)-(n0+jl)+P]
#pragma unroll
        for (int r = 0; r < 64; r++) {
            const int idx = tid + r * 256;
            const int il = idx >> 7, jl = idx & 127;
            dsm[il * PSTR + jl] =
                C2Pz[(size_t)(m0 + il) * (2 * kP) + (m0 + il) - (n0 + jl) + kP];
        }
        __syncthreads();
        const float* mrow = bias + (size_t)(z / kNH) * kS;
#pragma unroll
        for (int mt = 0; mt < MT; mt++)
#pragma unroll
            for (int nt = 0; nt < NT; nt++)
#pragma unroll
                for (int half = 0; half < 2; half++) {
                    const int il = mBase + mt * 16 + gi + half * 8;
                    const int jl = nBase + nt * 8 + 2 * gj;
                    const int m = m0 + il, n = n0 + jl;
                    float v0 = (acc[mt][nt][half * 2 + 0]
                                + dsm[il * PSTR + jl]) * kScale;
                    float v1 = (acc[mt][nt][half * 2 + 1]
                                + dsm[il * PSTR + jl + 1]) * kScale;
                    if (mrow[n] <= 0.f)     v0 = -1e9f;
                    if (mrow[n + 1] <= 0.f) v1 = -1e9f;
                    *reinterpret_cast<float2*>(
                        &C[(size_t)z * cStride + (size_t)m * N + n]) =
                        make_float2(v0, v1);
                }
        return;
    }

    // --- generic epilogue ---
#pragma unroll
    for (int mt = 0; mt < MT; mt++) {
#pragma unroll
        for (int nt = 0; nt < NT; nt++) {
#pragma unroll
            for (int half = 0; half < 2; half++) {
                const int m = m0 + mBase + mt * 16 + gi + half * 8;
                const int n = n0 + nBase + nt * 8 + 2 * gj;
                float v0 = acc[mt][nt][half * 2 + 0];
                float v1 = acc[mt][nt][half * 2 + 1];
                if (bias) {
                    const float* bz = bias + (size_t)(z % bMod) * biasStride;
                    v0 += bz[n]; v1 += bz[n + 1];
                }
                if constexpr (EPI == EPI_GELU) {
                    v0 = 0.5f * v0 * (1.f + erff(v0 * 0.70710678118654752f));
                    v1 = 0.5f * v1 * (1.f + erff(v1 * 0.70710678118654752f));
                }
                if constexpr (RND) { v0 = rnd_tf32(v0); v1 = rnd_tf32(v1); }
                size_t o;
                if constexpr (EPI == EPI_QKV) {
                    const int bb = m >> 9, s = m & 511, h = n >> 6, d = n & 63;
                    o = ((size_t)(bb * kNH + h) * kS + s) * kDH + d
                      + (size_t)z * cStride;
                } else if constexpr (EPI == EPI_POS) {
                    const int h = n >> 6, d = n & 63;
                    o = ((size_t)h * (2 * kP) + m) * kDH + d
                      + (size_t)z * cStride;
                } else if constexpr (EPI == EPI_CTX) {
                    const int bb = z / kNH, h = z % kNH;
                    o = ((size_t)bb * kS + m) * kH + h * kDH + n;
                } else {
                    o = (size_t)z * cStride + (size_t)m * N + n;
                }
                *reinterpret_cast<float2*>(&C[o]) = make_float2(v0, v1);
            }
        }
    }
}

// ---------------------------------------------------------------------------
// Plain row softmax on the assembled scores; probs written tf32-rounded.
// One block per (z, 16-row strip).
// ---------------------------------------------------------------------------
__global__ __launch_bounds__(256)
void softmax_kernel()
{
    const int z  = blockIdx.y;
    const int i0 = blockIdx.x * 16;
    const int tid = threadIdx.x;

    __shared__ float sc[16][513];
    __shared__ float red[16][17];
    __shared__ float invRow[16];

    float* Sz = g_scratch + OFF_S + (size_t)z * kS * kS;
#pragma unroll
    for (int r = 0; r < 32; r++) {
        const int idx = tid + r * 256;
        const int ii = idx >> 9, j = idx & 511;
        sc[ii][j] = Sz[(size_t)(i0 + ii) * kS + j];
    }
    __syncthreads();

    const int row = tid & 15, sg = tid >> 4;
    float mx = -1e30f;
#pragma unroll
    for (int q = 0; q < 32; q++) mx = fmaxf(mx, sc[row][sg * 32 + q]);
    red[sg][row] = mx;
    __syncthreads();
    mx = red[0][row];
#pragma unroll
    for (int s2 = 1; s2 < 16; s2++) mx = fmaxf(mx, red[s2][row]);
    __syncthreads();
    float sum = 0.f;
#pragma unroll
    for (int q = 0; q < 32; q++) {
        const float e = expf(sc[row][sg * 32 + q] - mx);
        sc[row][sg * 32 + q] = e;
        sum += e;
    }
    red[sg][row] = sum;
    __syncthreads();
    if (tid < 16) {
        float s = 0.f;
#pragma unroll
        for (int s2 = 0; s2 < 16; s2++) s += red[s2][tid];
        invRow[tid] = 1.f / s;
    }
    __syncthreads();
#pragma unroll
    for (int r = 0; r < 32; r++) {
        const int idx = tid + r * 256;
        const int ii = idx >> 9, j = idx & 511;
        Sz[(size_t)(i0 + ii) * kS + j] = rnd_tf32(sc[ii][j] * invRow[ii]);
    }
}

// ---------------------------------------------------------------------------
// out = LayerNorm(X + Y) * g + b; optional tf32-rounded extra copy.
// ---------------------------------------------------------------------------
__global__ void add_ln_kernel(const float* __restrict__ Xex, size_t xOff, size_t yOff,
                              const float* __restrict__ g, const float* __restrict__ bb,
                              float* __restrict__ outEx, size_t outOff,
                              int makeRounded, size_t rOff)
{
    const float* X = Xex ? Xex : (const float*)g_scratch + xOff;
    const float* Y = (const float*)g_scratch + yOff;
    float* O = outEx ? outEx : g_scratch + outOff;

    const size_t off = (size_t)blockIdx.x * kH;
    const int t = threadIdx.x;
    const float v0 = X[off + t]       + Y[off + t];
    const float v1 = X[off + t + 256] + Y[off + t + 256];
    const float v2 = X[off + t + 512] + Y[off + t + 512];

    __shared__ float red[256];
    red[t] = v0 + v1 + v2;
    __syncthreads();
    for (int s = 128; s > 0; s >>= 1) {
        if (t < s) red[t] += red[t + s];
        __syncthreads();
    }
    const float mean = red[0] * (1.f / 768.f);
    __syncthreads();

    const float d0 = v0 - mean, d1 = v1 - mean, d2 = v2 - mean;
    red[t] = d0 * d0 + d1 * d1 + d2 * d2;
    __syncthreads();
    for (int s = 128; s > 0; s >>= 1) {
        if (t < s) red[t] += red[t + s];
        __syncthreads();
    }
    const float rstd = rsqrtf(red[0] * (1.f / 768.f) + 1e-7f);

    const float o0 = d0 * rstd * g[t]       + bb[t];
    const float o1 = d1 * rstd * g[t + 256] + bb[t + 256];
    const float o2 = d2 * rstd * g[t + 512] + bb[t + 512];
    O[off + t]       = o0;
    O[off + t + 256] = o1;
    O[off + t + 512] = o2;
    if (makeRounded) {
        float* R = g_scratch + rOff;
        R[off + t]       = rnd_tf32(o0);
        R[off + t + 256] = rnd_tf32(o1);
        R[off + t + 512] = rnd_tf32(o2);
    }
}

// ---------------------------------------------------------------------------
// dynamic smem sizes (floats): 3 stages of As + Bs
//   NN BN=128: 3*(128*36 + 32*136)*4 = 107520 B
//   NN BN=64 : 3*(128*36 + 32*72)*4  =  82944 B
//   TB BN=128: 3*(128*36 + 128*36)*4 = 110592 B  (score staging 67584 B fits)
// ---------------------------------------------------------------------------
constexpr int SM_NN128 = 107520;
constexpr int SM_NN64  = 82944;
constexpr int SM_TB128 = 110592;

extern "C" void kernel_launch(void* const* d_in, const int* in_sizes, int n_in,
                              void* d_out, int out_size)
{
    const float* hs  = (const float*)d_in[0];
    const float* am  = (const float*)d_in[1];
    const float* pe  = (const float*)d_in[2];
    const float* Wq  = (const float*)d_in[3];
    const float* bq  = (const float*)d_in[4];
    const float* Wk  = (const float*)d_in[5];
    const float* bk  = (const float*)d_in[6];
    const float* Wv  = (const float*)d_in[7];
    const float* bv  = (const float*)d_in[8];
    const float* Wpk = (const float*)d_in[9];
    const float* Wpq = (const float*)d_in[10];
    const float* Wo  = (const float*)d_in[11];
    const float* bo  = (const float*)d_in[12];
    const float* g1  = (const float*)d_in[13];
    const float* be1 = (const float*)d_in[14];
    const float* W1  = (const float*)d_in[15];
    const float* b1  = (const float*)d_in[16];
    const float* W2  = (const float*)d_in[17];
    const float* b2  = (const float*)d_in[18];
    const float* g2  = (const float*)d_in[19];
    const float* be2 = (const float*)d_in[20];
    float* out = (float*)d_out;

    // opt-in dynamic smem (host attribute set; idempotent, capture-safe)
    auto qkvK  = gemm_tc<128,128,32,4,2,false,false,EPI_QKV,true>;
    auto posK  = gemm_tc<128,128,32,4,2,false,false,EPI_POS,true>;
    auto scoK  = gemm_tc<128,128,32,4,2,true,false,EPI_SCORE,false>;
    auto bandK = gemm_tc<128,128,32,4,2,true,true,EPI_NONE,false>;
    auto ctxK  = gemm_tc<128,64,32,4,2,false,false,EPI_CTX,true>;
    auto nnK   = gemm_tc<128,128,32,4,2,false,false,EPI_NONE,false>;
    auto gelK  = gemm_tc<128,128,32,4,2,false,false,EPI_GELU,true>;
    cudaFuncSetAttribute((const void*)qkvK,  cudaFuncAttributeMaxDynamicSharedMemorySize, SM_NN128);
    cudaFuncSetAttribute((const void*)posK,  cudaFuncAttributeMaxDynamicSharedMemorySize, SM_NN128);
    cudaFuncSetAttribute((const void*)scoK,  cudaFuncAttributeMaxDynamicSharedMemorySize, SM_TB128);
    cudaFuncSetAttribute((const void*)bandK, cudaFuncAttributeMaxDynamicSharedMemorySize, SM_TB128);
    cudaFuncSetAttribute((const void*)ctxK,  cudaFuncAttributeMaxDynamicSharedMemorySize, SM_NN64);
    cudaFuncSetAttribute((const void*)nnK,   cudaFuncAttributeMaxDynamicSharedMemorySize, SM_NN128);
    cudaFuncSetAttribute((const void*)gelK,  cudaFuncAttributeMaxDynamicSharedMemorySize, SM_NN128);

    // --- pre-round all external GEMM operands to tf32 ---
    preconvert_kernel<<<(int)(F4_TOTAL / 256), 256>>>(
        hs, pe, Wq, Wk, Wv, Wpk, Wpq, Wo, W1, W2, bq, bk, bv);

    // --- merged QKV (z selects weight/bias/output region) ---
    qkvK<<<dim3(kH/128, kBS/128, 3), 256, SM_NN128>>>(
        nullptr, OFF_CHS, nullptr, OFF_CWQ, nullptr, OFF_CB, kH,
        nullptr, OFF_Q, kBS, kH, kH, 0, SZ_W, 3, SZ_QKV);

    // --- merged position projections (z: PK/PQ) ---
    posK<<<dim3(kH/128, (2*kP)/128, 2), 256, SM_NN128>>>(
        nullptr, OFF_CPE, nullptr, OFF_CWPK, nullptr, NOBIAS, 0,
        nullptr, OFF_PK, 2*kP, kH, kH, 0, SZ_W, 2, SZ_POS);

    // --- c2p_all band: Q @ PK_h^T, live diagonal tiles only ---
    bandK<<<dim3(5, kS/128, kBH), 256, SM_TB128>>>(
        nullptr, OFF_Q, nullptr, OFF_PK, nullptr, NOBIAS, 0,
        nullptr, OFF_C2P, kS, 2*kP, kDH,
        (size_t)kS*kDH, (size_t)(2*kP)*kDH, kNH, (size_t)kS*(2*kP));
    // --- p2c_all band: K @ PQ_h^T ---
    bandK<<<dim3(5, kS/128, kBH), 256, SM_TB128>>>(
        nullptr, OFF_K, nullptr, OFF_PQ, nullptr, NOBIAS, 0,
        nullptr, OFF_P2C, kS, 2*kP, kDH,
        (size_t)kS*kDH, (size_t)(2*kP)*kDH, kNH, (size_t)kS*(2*kP));

    // --- scores = Q@K^T + gathered c2p + p2c, scaled + masked (fused) ---
    scoK<<<dim3(kS/128, kS/128, kBH), 256, SM_TB128>>>(
        nullptr, OFF_Q, nullptr, OFF_K, am, NOBIAS, 0,
        nullptr, OFF_S, kS, kS, kDH,
        (size_t)kS*kDH, (size_t)kS*kDH, kBH, (size_t)kS*kS);

    // --- softmax (in place), probs tf32-rounded ---
    softmax_kernel<<<dim3(kS/16, kBH), 256>>>();

    // --- ctx = probs @ V -> merged-head [B,S,H], tf32-rounded ---
    ctxK<<<dim3(1, kS/128, kBH), 256, SM_NN64>>>(
        nullptr, OFF_S, nullptr, OFF_V, nullptr, NOBIAS, 0,
        nullptr, OFF_CTX, kS, kDH, kS,
        (size_t)kS*kS, (size_t)kS*kDH, kBH, 0);

    // --- output projection + residual LN1 (H1 fp32 + tf32 copy) ---
    nnK<<<dim3(kH/128, kBS/128, 1), 256, SM_NN128>>>(
        nullptr, OFF_CTX, nullptr, OFF_CWO, bo, NOBIAS, 0,
        nullptr, OFF_T1, kBS, kH, kH, 0, 0, 1, 0);
    add_ln_kernel<<<kBS, 256>>>(hs, 0, OFF_T1, g1, be1, nullptr, OFF_H1, 1, OFF_H1R);

    // --- FFN ---
    gelK<<<dim3(kI/128, kBS/128, 1), 256, SM_NN128>>>(
        nullptr, OFF_H1R, nullptr, OFF_CW1, b1, NOBIAS, 0,
        nullptr, OFF_F1, kBS, kI, kH, 0, 0, 1, 0);
    nnK<<<dim3(kH/128, kBS/128, 1), 256, SM_NN128>>>(
        nullptr, OFF_F1, nullptr, OFF_CW2, b2, NOBIAS, 0,
        nullptr, OFF_T1, kBS, kH, kI, 0, 0, 1, 0);
    add_ln_kernel<<<kBS, 256>>>(nullptr, OFF_H1, OFF_T1, g2, be2, out, 0, 0, 0);
}

// round 11
// speedup vs baseline: 3.8302x; 1.0559x over previous
#include <cuda_runtime.h>
#include <math.h>
#include <stdint.h>

// ---------------------------------------------------------------------------
// DeBERTa layer. tf32 mma.sync GEMMs (3-stage cp.async) + fused
// flash-attention middle (c2c + c2p/p2c gather + online softmax + P@V in one
// kernel; no score/prob tensors ever hit DRAM).
// B=16 S=512 H=768 NH=12 DH=64 P=512 I=3072.
// scores[i,j] = q_i.k_j + q_i.PK[i-j+P] + k_j.PQ[j-i+P]  (no clip: |i-j|<=511)
// ---------------------------------------------------------------------------

constexpr int kB  = 16;
constexpr int kS  = 512;
constexpr int kH  = 768;
constexpr int kNH = 12;
constexpr int kDH = 64;
constexpr int kP  = 512;
constexpr int kI  = 3072;
constexpr int kBS = kB * kS;    // 8192
constexpr int kBH = kB * kNH;   // 192
constexpr float kScale = 0.07216878364870322f;  // 1/sqrt(3*64)

constexpr size_t NOBIAS = (size_t)-1;

// ---- scratch layout ----
constexpr size_t SZ_QKV = (size_t)kBH * kS * kDH;
constexpr size_t SZ_POS = (size_t)kNH * 2 * kP * kDH;
constexpr size_t SZ_CP  = (size_t)kBH * kS * 2 * kP;
constexpr size_t SZ_W   = (size_t)kH * kH;
constexpr size_t SZ_W1  = (size_t)kH * kI;

constexpr size_t OFF_Q    = 0;
constexpr size_t OFF_K    = OFF_Q + SZ_QKV;
constexpr size_t OFF_V    = OFF_K + SZ_QKV;
constexpr size_t OFF_PK   = OFF_V + SZ_QKV;
constexpr size_t OFF_PQ   = OFF_PK + SZ_POS;
constexpr size_t OFF_C2P  = OFF_PQ + SZ_POS;
constexpr size_t OFF_P2C  = OFF_C2P + SZ_CP;
constexpr size_t OFF_CTX  = OFF_P2C + SZ_CP;
constexpr size_t OFF_T1   = OFF_CTX + SZ_QKV;
constexpr size_t OFF_H1   = OFF_T1 + SZ_QKV;  // fp32 (residual path)
constexpr size_t OFF_H1R  = OFF_H1 + SZ_QKV;  // tf32-rounded (FFN1 A)
constexpr size_t OFF_F1   = OFF_C2P;          // alias: c2p dead after flash
constexpr size_t OFF_CHS  = OFF_H1R + SZ_QKV;
constexpr size_t OFF_CPE  = OFF_CHS + SZ_QKV;
constexpr size_t OFF_CWQ  = OFF_CPE + SZ_POS;
constexpr size_t OFF_CWK  = OFF_CWQ + SZ_W;
constexpr size_t OFF_CWV  = OFF_CWK + SZ_W;
constexpr size_t OFF_CWPK = OFF_CWV + SZ_W;
constexpr size_t OFF_CWPQ = OFF_CWPK + SZ_W;
constexpr size_t OFF_CWO  = OFF_CWPQ + SZ_W;
constexpr size_t OFF_CW1  = OFF_CWO + SZ_W;
constexpr size_t OFF_CW2  = OFF_CW1 + SZ_W1;
constexpr size_t OFF_CB   = OFF_CW2 + SZ_W1;
constexpr size_t TOTAL    = OFF_CB + 3 * kH;

__device__ __align__(256) float g_scratch[TOTAL];

enum { EPI_NONE = 0, EPI_GELU = 1, EPI_QKV = 2, EPI_POS = 3 };

__device__ __forceinline__ uint32_t cvt_tf32(float x) {
    uint32_t u;
    asm("cvt.rna.tf32.f32 %0, %1;" : "=r"(u) : "f"(x));
    return u;
}
__device__ __forceinline__ float rnd_tf32(float x) {
    return __uint_as_float(cvt_tf32(x));
}

__device__ __forceinline__ void mma_tf32(float (&d)[4], const uint32_t (&a)[4],
                                         const uint32_t (&b)[2]) {
    asm volatile(
        "mma.sync.aligned.m16n8k8.row.col.f32.tf32.tf32.f32 "
        "{%0,%1,%2,%3}, {%4,%5,%6,%7}, {%8,%9}, {%0,%1,%2,%3};"
        : "+f"(d[0]), "+f"(d[1]), "+f"(d[2]), "+f"(d[3])
        : "r"(a[0]), "r"(a[1]), "r"(a[2]), "r"(a[3]), "r"(b[0]), "r"(b[1]));
}

__device__ __forceinline__ void cp_async16(uint32_t smem, const void* g) {
    asm volatile("cp.async.cg.shared.global [%0], [%1], 16;" :: "r"(smem), "l"(g));
}
__device__ __forceinline__ void cp_commit() {
    asm volatile("cp.async.commit_group;" ::: "memory");
}
__device__ __forceinline__ void cp_wait1() {
    asm volatile("cp.async.wait_group 1;" ::: "memory");
}

// ---------------------------------------------------------------------------
// Pre-round external GEMM operands to tf32 (RNA) into scratch.
// ---------------------------------------------------------------------------
constexpr size_t F4_HS = SZ_QKV / 4;
constexpr size_t F4_PE = SZ_POS / 4;
constexpr size_t F4_W  = SZ_W / 4;
constexpr size_t F4_W1 = SZ_W1 / 4;
constexpr size_t F4_TOTAL = F4_HS + F4_PE + 6 * F4_W + 2 * F4_W1;

__global__ __launch_bounds__(256)
void preconvert_kernel(const float* __restrict__ hs, const float* __restrict__ pe,
                       const float* __restrict__ Wq, const float* __restrict__ Wk,
                       const float* __restrict__ Wv, const float* __restrict__ Wpk,
                       const float* __restrict__ Wpq, const float* __restrict__ Wo,
                       const float* __restrict__ W1, const float* __restrict__ W2,
                       const float* __restrict__ bq, const float* __restrict__ bk,
                       const float* __restrict__ bv)
{
    size_t i = (size_t)blockIdx.x * 256 + threadIdx.x;
    if (i < 576) {
        float4* cb = reinterpret_cast<float4*>(g_scratch + OFF_CB);
        if (i < 192)      cb[i] = reinterpret_cast<const float4*>(bq)[i];
        else if (i < 384) cb[i] = reinterpret_cast<const float4*>(bk)[i - 192];
        else              cb[i] = reinterpret_cast<const float4*>(bv)[i - 384];
    }
    const float* src; float* dst;
    if (i < F4_HS)                 { src = hs;  dst = g_scratch + OFF_CHS; }
    else if ((i -= F4_HS) < F4_PE) { src = pe;  dst = g_scratch + OFF_CPE; }
    else if ((i -= F4_PE) < F4_W)  { src = Wq;  dst = g_scratch + OFF_CWQ; }
    else if ((i -= F4_W) < F4_W)   { src = Wk;  dst = g_scratch + OFF_CWK; }
    else if ((i -= F4_W) < F4_W)   { src = Wv;  dst = g_scratch + OFF_CWV; }
    else if ((i -= F4_W) < F4_W)   { src = Wpk; dst = g_scratch + OFF_CWPK; }
    else if ((i -= F4_W) < F4_W)   { src = Wpq; dst = g_scratch + OFF_CWPQ; }
    else if ((i -= F4_W) < F4_W)   { src = Wo;  dst = g_scratch + OFF_CWO; }
    else if ((i -= F4_W) < F4_W1)  { src = W1;  dst = g_scratch + OFF_CW1; }
    else { i -= F4_W1;               src = W2;  dst = g_scratch + OFF_CW2; }
    float4 v = reinterpret_cast<const float4*>(src)[i];
    v.x = rnd_tf32(v.x); v.y = rnd_tf32(v.y);
    v.z = rnd_tf32(v.z); v.w = rnd_tf32(v.w);
    reinterpret_cast<float4*>(dst)[i] = v;
}

// ---------------------------------------------------------------------------
// Pipelined tensor-core GEMM (unchanged from R10, minus score/ctx epilogues).
// ---------------------------------------------------------------------------
template<int BM, int BN, int BK, int WM, int WN, bool TB, bool DIAG, int EPI, bool RND>
__global__ __launch_bounds__(256, 2)
void gemm_tc(const float* __restrict__ Aex, size_t aOff,
             const float* __restrict__ Bex, size_t bOff,
             const float* __restrict__ biasEx, size_t biasOff, size_t biasStride,
             float* __restrict__ Cex, size_t cOff,
             int M, int N, int K,
             size_t aStride, size_t bStride, int bMod, size_t cStride)
{
    static_assert(WM * WN * 32 == 256, "");
    constexpr int WTM = BM / WM;
    constexpr int WTN = BN / WN;
    constexpr int MT  = WTM / 16;
    constexpr int NT  = WTN / 8;
    constexpr int ASTR  = BK + 4;
    constexpr int BSTR  = TB ? (BK + 4) : (BN + 8);
    constexpr int BROWS = TB ? BN : BK;
    constexpr int ASTAGE = BM * ASTR;
    constexpr int BSTAGE = BROWS * BSTR;
    constexpr int LA = (BM * BK) / (4 * 256);
    constexpr int LB = TB ? (BN * BK) / (4 * 256) : (BK * BN) / (4 * 256);

    extern __shared__ __align__(16) float dsm[];
    float* As = dsm;
    float* Bs = dsm + 3 * ASTAGE;

    const float* A  = Aex ? Aex : (const float*)g_scratch + aOff;
    const float* Bp = Bex ? Bex : (const float*)g_scratch + bOff;
    float*       C  = Cex ? Cex : g_scratch + cOff;
    const float* bias = biasEx ? biasEx
                      : (biasOff != NOBIAS ? (const float*)g_scratch + biasOff
                                           : nullptr);

    const int z = blockIdx.z;
    A  += (size_t)z * aStride;
    Bp += (size_t)(z % bMod) * bStride;

    const int m0 = blockIdx.y * BM;
    const int n0 = DIAG ? (blockIdx.y * BM + blockIdx.x * BN) : (blockIdx.x * BN);
    const int tid  = threadIdx.x;
    const int warp = tid >> 5;
    const int lane = tid & 31;
    const int wm = warp % WM, wn = warp / WM;
    const int mBase = wm * WTM, nBase = wn * WTN;
    const int gi = lane >> 2, gj = lane & 3;

    const uint32_t sAs = (uint32_t)__cvta_generic_to_shared(As);
    const uint32_t sBs = (uint32_t)__cvta_generic_to_shared(Bs);

    const int aRow = tid >> 3, aKg = tid & 7;
    const int bKr = TB ? 0 : (tid / (BN / 4));
    const int bNg = TB ? 0 : (tid % (BN / 4));

    auto load_stage = [&](int stage, int kblk) {
#pragma unroll
        for (int r = 0; r < LA; r++) {
            const int row = aRow + r * 32;
            cp_async16(sAs + (uint32_t)(stage * ASTAGE + row * ASTR + aKg * 4) * 4,
                       A + (size_t)(m0 + row) * K + kblk + aKg * 4);
        }
        if constexpr (TB) {
#pragma unroll
            for (int r = 0; r < LB; r++) {
                const int row = aRow + r * 32;
                cp_async16(sBs + (uint32_t)(stage * BSTAGE + row * BSTR + aKg * 4) * 4,
                           Bp + (size_t)(n0 + row) * K + kblk + aKg * 4);
            }
        } else {
#pragma unroll
            for (int r = 0; r < LB; r++) {
                const int kr = bKr + r * (1024 / BN);
                cp_async16(sBs + (uint32_t)(stage * BSTAGE + kr * BSTR + bNg * 4) * 4,
                           Bp + (size_t)(kblk + kr) * N + n0 + bNg * 4);
            }
        }
    };

    float acc[MT][NT][4];
#pragma unroll
    for (int i = 0; i < MT; i++)
#pragma unroll
        for (int j = 0; j < NT; j++)
#pragma unroll
            for (int r = 0; r < 4; r++) acc[i][j][r] = 0.f;

    load_stage(0, 0);
    cp_commit();
    load_stage(1, BK);
    cp_commit();

    const int TSTEPS = K / BK;
    for (int t = 0; t < TSTEPS; t++) {
        cp_wait1();
        __syncthreads();
        if (t + 2 < TSTEPS) load_stage((t + 2) % 3, (t + 2) * BK);
        cp_commit();

        const int cur = t % 3;
        const uint32_t* Ac = reinterpret_cast<const uint32_t*>(As) + cur * ASTAGE;
        const uint32_t* Bc = reinterpret_cast<const uint32_t*>(Bs) + cur * BSTAGE;
#pragma unroll
        for (int ks = 0; ks < BK / 8; ks++) {
            const int kk = ks * 8;
            uint32_t af[MT][4];
#pragma unroll
            for (int mt = 0; mt < MT; mt++) {
                const int r0 = (mBase + mt * 16 + gi) * ASTR + kk + gj;
                af[mt][0] = Ac[r0];
                af[mt][1] = Ac[r0 + 8 * ASTR];
                af[mt][2] = Ac[r0 + 4];
                af[mt][3] = Ac[r0 + 8 * ASTR + 4];
            }
            uint32_t bf[NT][2];
#pragma unroll
            for (int nt = 0; nt < NT; nt++) {
                const int col = nBase + nt * 8 + gi;
                if constexpr (TB) {
                    const int b0 = col * BSTR + kk + gj;
                    bf[nt][0] = Bc[b0];
                    bf[nt][1] = Bc[b0 + 4];
                } else {
                    const int b0 = (kk + gj) * BSTR + col;
                    bf[nt][0] = Bc[b0];
                    bf[nt][1] = Bc[b0 + 4 * BSTR];
                }
            }
#pragma unroll
            for (int mt = 0; mt < MT; mt++)
#pragma unroll
                for (int nt = 0; nt < NT; nt++)
                    mma_tf32(acc[mt][nt], af[mt], bf[nt]);
        }
    }

#pragma unroll
    for (int mt = 0; mt < MT; mt++) {
#pragma unroll
        for (int nt = 0; nt < NT; nt++) {
#pragma unroll
            for (int half = 0; half < 2; half++) {
                const int m = m0 + mBase + mt * 16 + gi + half * 8;
                const int n = n0 + nBase + nt * 8 + 2 * gj;
                float v0 = acc[mt][nt][half * 2 + 0];
                float v1 = acc[mt][nt][half * 2 + 1];
                if (bias) {
                    const float* bz = bias + (size_t)(z % bMod) * biasStride;
                    v0 += bz[n]; v1 += bz[n + 1];
                }
                if constexpr (EPI == EPI_GELU) {
                    v0 = 0.5f * v0 * (1.f + erff(v0 * 0.70710678118654752f));
                    v1 = 0.5f * v1 * (1.f + erff(v1 * 0.70710678118654752f));
                }
                if constexpr (RND) { v0 = rnd_tf32(v0); v1 = rnd_tf32(v1); }
                size_t o;
                if constexpr (EPI == EPI_QKV) {
                    const int bb = m >> 9, s = m & 511, h = n >> 6, d = n & 63;
                    o = ((size_t)(bb * kNH + h) * kS + s) * kDH + d
                      + (size_t)z * cStride;
                } else if constexpr (EPI == EPI_POS) {
                    const int h = n >> 6, d = n & 63;
                    o = ((size_t)h * (2 * kP) + m) * kDH + d
                      + (size_t)z * cStride;
                } else {
                    o = (size_t)z * cStride + (size_t)m * N + n;
                }
                *reinterpret_cast<float2*>(&C[o]) = make_float2(v0, v1);
            }
        }
    }
}

// ---------------------------------------------------------------------------
// Fused flash attention: per (z, 128-row i-tile):
//   loop j-tiles: S = Q@K^T + p2c + c2p (staged), scale+mask, online softmax,
//   ctx += P@V. Writes merged-head CTX (tf32-rounded). No score DRAM traffic.
// 8 warps x 16 rows each (row stats warp-local; quad shuffles only).
// smem: Qs[128][68] Ks[128][68] Vs[128][72] Ps[128][132] = 174080 B.
// ---------------------------------------------------------------------------
constexpr int FA_QS = 0;
constexpr int FA_KS = 128 * 68;
constexpr int FA_VS = FA_KS + 128 * 68;
constexpr int FA_PS = FA_VS + 128 * 72;
constexpr int FA_SMEM = (FA_PS + 128 * 132) * 4;   // 174080 bytes

__global__ __launch_bounds__(256, 1)
void flash_attn_kernel(const float* __restrict__ mask)
{
    extern __shared__ __align__(16) float sm[];
    float* Qs = sm + FA_QS;
    float* Ks = sm + FA_KS;
    float* Vs = sm + FA_VS;
    float* Ps = sm + FA_PS;

    const int z  = blockIdx.y;
    const int i0 = blockIdx.x * 128;
    const int tid  = threadIdx.x;
    const int warp = tid >> 5;
    const int lane = tid & 31;
    const int gi = lane >> 2, gj = lane & 3;
    const int mBase = warp * 16;

    const float* Qz = g_scratch + OFF_Q + (size_t)z * kS * kDH;
    const float* Kz = g_scratch + OFF_K + (size_t)z * kS * kDH;
    const float* Vz = g_scratch + OFF_V + (size_t)z * kS * kDH;
    const float* C2Pz = g_scratch + OFF_C2P + (size_t)z * kS * (2 * kP);
    const float* P2Cz = g_scratch + OFF_P2C + (size_t)z * kS * (2 * kP);
    const float* mrow = mask + (size_t)(z / kNH) * kS;

    // load Q tile once: 128 rows x 16 float4
#pragma unroll
    for (int r = 0; r < 8; r++) {
        const int idx = tid + r * 256;
        const int row = idx >> 4, f4 = idx & 15;
        *reinterpret_cast<float4*>(&Qs[row * 68 + f4 * 4]) =
            *reinterpret_cast<const float4*>(&Qz[(size_t)(i0 + row) * kDH + f4 * 4]);
    }

    float ctx[8][4];
#pragma unroll
    for (int n = 0; n < 8; n++)
#pragma unroll
        for (int c = 0; c < 4; c++) ctx[n][c] = 0.f;
    float rm[2] = {-1e30f, -1e30f};
    float rs[2] = {0.f, 0.f};

    for (int jt = 0; jt < 4; jt++) {
        const int j0 = jt * 128;
        __syncthreads();   // prior iteration's smem reads complete
        // stage K, V tiles
#pragma unroll
        for (int r = 0; r < 8; r++) {
            const int idx = tid + r * 256;
            const int row = idx >> 4, f4 = idx & 15;
            *reinterpret_cast<float4*>(&Ks[row * 68 + f4 * 4]) =
                *reinterpret_cast<const float4*>(&Kz[(size_t)(j0 + row) * kDH + f4 * 4]);
            *reinterpret_cast<float4*>(&Vs[row * 72 + f4 * 4]) =
                *reinterpret_cast<const float4*>(&Vz[(size_t)(j0 + row) * kDH + f4 * 4]);
        }
        __syncthreads();

        // ---- S = Q @ K^T : warp tile 16x128, MT=1, NT=16 ----
        float accS[16][4];
#pragma unroll
        for (int n = 0; n < 16; n++)
#pragma unroll
            for (int c = 0; c < 4; c++) accS[n][c] = 0.f;
        const uint32_t* Qu = reinterpret_cast<const uint32_t*>(Qs);
        const uint32_t* Ku = reinterpret_cast<const uint32_t*>(Ks);
#pragma unroll
        for (int ks = 0; ks < 8; ks++) {
            const int kk = ks * 8;
            uint32_t af[4];
            const int r0 = (mBase + gi) * 68 + kk + gj;
            af[0] = Qu[r0];
            af[1] = Qu[r0 + 8 * 68];
            af[2] = Qu[r0 + 4];
            af[3] = Qu[r0 + 8 * 68 + 4];
#pragma unroll
            for (int nt = 0; nt < 16; nt++) {
                uint32_t bf[2];
                const int b0 = (nt * 8 + gi) * 68 + kk + gj;
                bf[0] = Ku[b0];
                bf[1] = Ku[b0 + 4];
                mma_tf32(accS[nt], af, bf);
            }
        }

        // ---- stage p2c tile: Ps[jl*132+il] = p2c_all[j0+jl][(j0+jl)-(i0+il)+P]
#pragma unroll
        for (int r = 0; r < 64; r++) {
            const int idx = tid + r * 256;
            const int jl = idx >> 7, il = idx & 127;
            Ps[jl * 132 + il] =
                P2Cz[(size_t)(j0 + jl) * (2 * kP) + (j0 + jl) - (i0 + il) + kP];
        }
        __syncthreads();
#pragma unroll
        for (int nt = 0; nt < 16; nt++)
#pragma unroll
            for (int half = 0; half < 2; half++) {
                const int il = mBase + gi + half * 8;
                const int jl = nt * 8 + 2 * gj;
                accS[nt][half * 2 + 0] += Ps[jl * 132 + il];
                accS[nt][half * 2 + 1] += Ps[(jl + 1) * 132 + il];
            }
        __syncthreads();
        // ---- stage c2p tile: Ps[il*132+jl] = c2p_all[i0+il][(i0+il)-(j0+jl)+P]
#pragma unroll
        for (int r = 0; r < 64; r++) {
            const int idx = tid + r * 256;
            const int il = idx >> 7, jl = idx & 127;
            Ps[il * 132 + jl] =
                C2Pz[(size_t)(i0 + il) * (2 * kP) + (i0 + il) - (j0 + jl) + kP];
        }
        __syncthreads();
        // ---- add c2p, scale, mask ----
#pragma unroll
        for (int nt = 0; nt < 16; nt++)
#pragma unroll
            for (int half = 0; half < 2; half++) {
                const int il = mBase + gi + half * 8;
                const int jl = nt * 8 + 2 * gj;
                float s0 = (accS[nt][half * 2 + 0] + Ps[il * 132 + jl]) * kScale;
                float s1 = (accS[nt][half * 2 + 1] + Ps[il * 132 + jl + 1]) * kScale;
                if (mrow[j0 + jl] <= 0.f)     s0 = -1e9f;
                if (mrow[j0 + jl + 1] <= 0.f) s1 = -1e9f;
                accS[nt][half * 2 + 0] = s0;
                accS[nt][half * 2 + 1] = s1;
            }

        // ---- online softmax update (rows warp-local; quad shuffles) ----
#pragma unroll
        for (int half = 0; half < 2; half++) {
            float tmax = -1e30f;
#pragma unroll
            for (int nt = 0; nt < 16; nt++)
                tmax = fmaxf(tmax, fmaxf(accS[nt][half * 2], accS[nt][half * 2 + 1]));
            tmax = fmaxf(tmax, __shfl_xor_sync(0xFFFFFFFFu, tmax, 1));
            tmax = fmaxf(tmax, __shfl_xor_sync(0xFFFFFFFFu, tmax, 2));
            const float mNew = fmaxf(rm[half], tmax);
            const float alpha = __expf(rm[half] - mNew);
            float lsum = 0.f;
#pragma unroll
            for (int nt = 0; nt < 16; nt++) {
                const float e0 = __expf(accS[nt][half * 2 + 0] - mNew);
                const float e1 = __expf(accS[nt][half * 2 + 1] - mNew);
                accS[nt][half * 2 + 0] = e0;
                accS[nt][half * 2 + 1] = e1;
                lsum += e0 + e1;
            }
            lsum += __shfl_xor_sync(0xFFFFFFFFu, lsum, 1);
            lsum += __shfl_xor_sync(0xFFFFFFFFu, lsum, 2);
            rs[half] = rs[half] * alpha + lsum;
            rm[half] = mNew;
#pragma unroll
            for (int n = 0; n < 8; n++) {
                ctx[n][half * 2 + 0] *= alpha;
                ctx[n][half * 2 + 1] *= alpha;
            }
        }

        __syncthreads();   // c2p reads done before P overwrite
        // ---- write P (tf32-rounded) m-major for a-fragment reload ----
#pragma unroll
        for (int nt = 0; nt < 16; nt++)
#pragma unroll
            for (int half = 0; half < 2; half++) {
                const int il = mBase + gi + half * 8;
                const int jl = nt * 8 + 2 * gj;
                *reinterpret_cast<float2*>(&Ps[il * 132 + jl]) =
                    make_float2(rnd_tf32(accS[nt][half * 2 + 0]),
                                rnd_tf32(accS[nt][half * 2 + 1]));
            }
        __syncthreads();

        // ---- ctx += P @ V : warp tile 16x64, k=128 ----
        const uint32_t* Pu = reinterpret_cast<const uint32_t*>(Ps);
        const uint32_t* Vu = reinterpret_cast<const uint32_t*>(Vs);
#pragma unroll
        for (int ks = 0; ks < 16; ks++) {
            const int kk = ks * 8;
            uint32_t af[4];
            const int r0 = (mBase + gi) * 132 + kk + gj;
            af[0] = Pu[r0];
            af[1] = Pu[r0 + 8 * 132];
            af[2] = Pu[r0 + 4];
            af[3] = Pu[r0 + 8 * 132 + 4];
#pragma unroll
            for (int nt = 0; nt < 8; nt++) {
                uint32_t bf[2];
                const int b0 = (kk + gj) * 72 + nt * 8 + gi;
                bf[0] = Vu[b0];
                bf[1] = Vu[b0 + 4 * 72];
                mma_tf32(ctx[nt], af, bf);
            }
        }
    }

    // ---- finalize: ctx /= sum; write merged-head [B,S,H], tf32-rounded ----
    const int bb = z / kNH, h = z % kNH;
    const float inv0 = 1.f / rs[0], inv1 = 1.f / rs[1];
    float* Cg = g_scratch + OFF_CTX;
#pragma unroll
    for (int nt = 0; nt < 8; nt++)
#pragma unroll
        for (int half = 0; half < 2; half++) {
            const int m = i0 + mBase + gi + half * 8;
            const int d = nt * 8 + 2 * gj;
            const float inv = half ? inv1 : inv0;
            const float v0 = rnd_tf32(ctx[nt][half * 2 + 0] * inv);
            const float v1 = rnd_tf32(ctx[nt][half * 2 + 1] * inv);
            *reinterpret_cast<float2*>(
                &Cg[((size_t)bb * kS + m) * kH + h * kDH + d]) =
                make_float2(v0, v1);
        }
}

// ---------------------------------------------------------------------------
// out = LayerNorm(X + Y) * g + b; optional tf32-rounded extra copy.
// ---------------------------------------------------------------------------
__global__ void add_ln_kernel(const float* __restrict__ Xex, size_t xOff, size_t yOff,
                              const float* __restrict__ g, const float* __restrict__ bb,
                              float* __restrict__ outEx, size_t outOff,
                              int makeRounded, size_t rOff)
{
    const float* X = Xex ? Xex : (const float*)g_scratch + xOff;
    const float* Y = (const float*)g_scratch + yOff;
    float* O = outEx ? outEx : g_scratch + outOff;

    const size_t off = (size_t)blockIdx.x * kH;
    const int t = threadIdx.x;
    const float v0 = X[off + t]       + Y[off + t];
    const float v1 = X[off + t + 256] + Y[off + t + 256];
    const float v2 = X[off + t + 512] + Y[off + t + 512];

    __shared__ float red[256];
    red[t] = v0 + v1 + v2;
    __syncthreads();
    for (int s = 128; s > 0; s >>= 1) {
        if (t < s) red[t] += red[t + s];
        __syncthreads();
    }
    const float mean = red[0] * (1.f / 768.f);
    __syncthreads();

    const float d0 = v0 - mean, d1 = v1 - mean, d2 = v2 - mean;
    red[t] = d0 * d0 + d1 * d1 + d2 * d2;
    __syncthreads();
    for (int s = 128; s > 0; s >>= 1) {
        if (t < s) red[t] += red[t + s];
        __syncthreads();
    }
    const float rstd = rsqrtf(red[0] * (1.f / 768.f) + 1e-7f);

    const float o0 = d0 * rstd * g[t]       + bb[t];
    const float o1 = d1 * rstd * g[t + 256] + bb[t + 256];
    const float o2 = d2 * rstd * g[t + 512] + bb[t + 512];
    O[off + t]       = o0;
    O[off + t + 256] = o1;
    O[off + t + 512] = o2;
    if (makeRounded) {
        float* R = g_scratch + rOff;
        R[off + t]       = rnd_tf32(o0);
        R[off + t + 256] = rnd_tf32(o1);
        R[off + t + 512] = rnd_tf32(o2);
    }
}

// ---------------------------------------------------------------------------
constexpr int SM_NN128 = 107520;
constexpr int SM_TB128 = 110592;

extern "C" void kernel_launch(void* const* d_in, const int* in_sizes, int n_in,
                              void* d_out, int out_size)
{
    const float* hs  = (const float*)d_in[0];
    const float* am  = (const float*)d_in[1];
    const float* pe  = (const float*)d_in[2];
    const float* Wq  = (const float*)d_in[3];
    const float* bq  = (const float*)d_in[4];
    const float* Wk  = (const float*)d_in[5];
    const float* bk  = (const float*)d_in[6];
    const float* Wv  = (const float*)d_in[7];
    const float* bv  = (const float*)d_in[8];
    const float* Wpk = (const float*)d_in[9];
    const float* Wpq = (const float*)d_in[10];
    const float* Wo  = (const float*)d_in[11];
    const float* bo  = (const float*)d_in[12];
    const float* g1  = (const float*)d_in[13];
    const float* be1 = (const float*)d_in[14];
    const float* W1  = (const float*)d_in[15];
    const float* b1  = (const float*)d_in[16];
    const float* W2  = (const float*)d_in[17];
    const float* b2  = (const float*)d_in[18];
    const float* g2  = (const float*)d_in[19];
    const float* be2 = (const float*)d_in[20];
    float* out = (float*)d_out;

    auto qkvK  = gemm_tc<128,128,32,4,2,false,false,EPI_QKV,true>;
    auto posK  = gemm_tc<128,128,32,4,2,false,false,EPI_POS,true>;
    auto bandK = gemm_tc<128,128,32,4,2,true,true,EPI_NONE,false>;
    auto nnK   = gemm_tc<128,128,32,4,2,false,false,EPI_NONE,false>;
    auto gelK  = gemm_tc<128,128,32,4,2,false,false,EPI_GELU,true>;
    cudaFuncSetAttribute((const void*)qkvK,  cudaFuncAttributeMaxDynamicSharedMemorySize, SM_NN128);
    cudaFuncSetAttribute((const void*)posK,  cudaFuncAttributeMaxDynamicSharedMemorySize, SM_NN128);
    cudaFuncSetAttribute((const void*)bandK, cudaFuncAttributeMaxDynamicSharedMemorySize, SM_TB128);
    cudaFuncSetAttribute((const void*)nnK,   cudaFuncAttributeMaxDynamicSharedMemorySize, SM_NN128);
    cudaFuncSetAttribute((const void*)gelK,  cudaFuncAttributeMaxDynamicSharedMemorySize, SM_NN128);
    cudaFuncSetAttribute((const void*)flash_attn_kernel,
                         cudaFuncAttributeMaxDynamicSharedMemorySize, FA_SMEM);

    // --- pre-round all external GEMM operands to tf32 ---
    preconvert_kernel<<<(int)(F4_TOTAL / 256), 256>>>(
        hs, pe, Wq, Wk, Wv, Wpk, Wpq, Wo, W1, W2, bq, bk, bv);

    // --- merged QKV (z selects weight/bias/output region) ---
    qkvK<<<dim3(kH/128, kBS/128, 3), 256, SM_NN128>>>(
        nullptr, OFF_CHS, nullptr, OFF_CWQ, nullptr, OFF_CB, kH,
        nullptr, OFF_Q, kBS, kH, kH, 0, SZ_W, 3, SZ_QKV);

    // --- merged position projections (z: PK/PQ) ---
    posK<<<dim3(kH/128, (2*kP)/128, 2), 256, SM_NN128>>>(
        nullptr, OFF_CPE, nullptr, OFF_CWPK, nullptr, NOBIAS, 0,
        nullptr, OFF_PK, 2*kP, kH, kH, 0, SZ_W, 2, SZ_POS);

    // --- c2p_all / p2c_all bands (diagonal tiles only) ---
    bandK<<<dim3(5, kS/128, kBH), 256, SM_TB128>>>(
        nullptr, OFF_Q, nullptr, OFF_PK, nullptr, NOBIAS, 0,
        nullptr, OFF_C2P, kS, 2*kP, kDH,
        (size_t)kS*kDH, (size_t)(2*kP)*kDH, kNH, (size_t)kS*(2*kP));
    bandK<<<dim3(5, kS/128, kBH), 256, SM_TB128>>>(
        nullptr, OFF_K, nullptr, OFF_PQ, nullptr, NOBIAS, 0,
        nullptr, OFF_P2C, kS, 2*kP, kDH,
        (size_t)kS*kDH, (size_t)(2*kP)*kDH, kNH, (size_t)kS*(2*kP));

    // --- fused flash attention: scores+softmax+P@V, writes CTX ---
    flash_attn_kernel<<<dim3(kS/128, kBH), 256, FA_SMEM>>>(am);

    // --- output projection + residual LN1 (H1 fp32 + tf32 copy) ---
    nnK<<<dim3(kH/128, kBS/128, 1), 256, SM_NN128>>>(
        nullptr, OFF_CTX, nullptr, OFF_CWO, bo, NOBIAS, 0,
        nullptr, OFF_T1, kBS, kH, kH, 0, 0, 1, 0);
    add_ln_kernel<<<kBS, 256>>>(hs, 0, OFF_T1, g1, be1, nullptr, OFF_H1, 1, OFF_H1R);

    // --- FFN ---
    gelK<<<dim3(kI/128, kBS/128, 1), 256, SM_NN128>>>(
        nullptr, OFF_H1R, nullptr, OFF_CW1, b1, NOBIAS, 0,
        nullptr, OFF_F1, kBS, kI, kH, 0, 0, 1, 0);
    nnK<<<dim3(kH/128, kBS/128, 1), 256, SM_NN128>>>(
        nullptr, OFF_F1, nullptr, OFF_CW2, b2, NOBIAS, 0,
        nullptr, OFF_T1, kBS, kH, kI, 0, 0, 1, 0);
    add_ln_kernel<<<kBS, 256>>>(nullptr, OFF_H1, OFF_T1, g2, be2, out, 0, 0, 0);
}